// round 12
// baseline (speedup 1.0000x reference)
#include <cuda_runtime.h>
#include <cuda_bf16.h>
#include <math.h>
#include <stdint.h>

#define HIDDEN 4096
#define NH 32
#define NKV 8
#define HD 128
#define BB 2
#define SS 2048
#define MROWS (BB*SS)   /* 4096 */
#define NQKV 6144       /* 4096 + 1024 + 1024 */

// ---------------- scratch -----------------------------------------------------
__device__ float g_QKV[(size_t)MROWS * NQKV];
__device__ float g_A[(size_t)MROWS * NH * HD];
__device__ uint32_t g_Xp   [(size_t)MROWS * HIDDEN];
__device__ uint32_t g_Apk  [(size_t)MROWS * NH * HD];
__device__ uint32_t g_Wqkvp[(size_t)NQKV * HIDDEN];
__device__ uint32_t g_Wop  [(size_t)HIDDEN * NH * HD];
__device__ uint4 g_Qpk[(size_t)BB * NH * 128 * 8 * 64];
__device__ uint4 g_Kpk[(size_t)BB * NKV * 256 * 8 * 32];
__device__ uint4 g_Vtp[(size_t)BB * NKV * 32 * 16 * 4 * 32];

__device__ __forceinline__ uint32_t f2tf32(float f) {
    uint32_t r; asm("cvt.rna.tf32.f32 %0, %1;" : "=r"(r) : "f"(f)); return r;
}
__device__ __forceinline__ uint32_t bfpair(float x0, float x1) {
    __nv_bfloat162 h; h.x = __float2bfloat16(x0); h.y = __float2bfloat16(x1);
    return *(uint32_t*)&h;
}
__device__ __forceinline__ uint32_t bfpair_lo(float x0, float x1, uint32_t hi) {
    __nv_bfloat162 h = *(__nv_bfloat162*)&hi;
    return bfpair(x0 - __bfloat162float(h.x), x1 - __bfloat162float(h.y));
}

__device__ __forceinline__ void mma16n8k8(float* d, const uint32_t* a,
                                          uint32_t b0, uint32_t b1) {
    asm volatile(
        "mma.sync.aligned.m16n8k8.row.col.f32.tf32.tf32.f32 "
        "{%0,%1,%2,%3}, {%4,%5,%6,%7}, {%8,%9}, {%0,%1,%2,%3};"
        : "+f"(d[0]), "+f"(d[1]), "+f"(d[2]), "+f"(d[3])
        : "r"(a[0]), "r"(a[1]), "r"(a[2]), "r"(a[3]), "r"(b0), "r"(b1));
}
__device__ __forceinline__ void mma_bf16(float* d, const uint32_t* a,
                                         uint32_t b0, uint32_t b1) {
    asm volatile(
        "mma.sync.aligned.m16n8k16.row.col.f32.bf16.bf16.f32 "
        "{%0,%1,%2,%3}, {%4,%5,%6,%7}, {%8,%9}, {%0,%1,%2,%3};"
        : "+f"(d[0]), "+f"(d[1]), "+f"(d[2]), "+f"(d[3])
        : "r"(a[0]), "r"(a[1]), "r"(a[2]), "r"(a[3]), "r"(b0), "r"(b1));
}

// ---------------- tf32 packing (GEMM operands) ---------------------------------
__global__ __launch_bounds__(256) void pack_a(const float* __restrict__ X,
                                              uint32_t* __restrict__ Xp,
                                              int M, int K)
{
    int idx = blockIdx.x * 256 + threadIdx.x;
    int total = (M >> 4) * (K >> 3) * 32;
    if (idx >= total) return;
    int lane = idx & 31, t = idx >> 5;
    int KT = K >> 3;
    int kt = t % KT, mt = t / KT;
    int g = lane >> 2, tg = lane & 3;
    size_t r0 = (size_t)(mt * 16 + g) * K + kt * 8 + tg;
    uint4 v;
    v.x = f2tf32(X[r0]);
    v.y = f2tf32(X[r0 + (size_t)8 * K]);
    v.z = f2tf32(X[r0 + 4]);
    v.w = f2tf32(X[r0 + (size_t)8 * K + 4]);
    ((uint4*)Xp)[(size_t)t * 32 + lane] = v;
}

__global__ __launch_bounds__(256) void pack_b(const float* __restrict__ W,
                                              uint32_t* __restrict__ Wp,
                                              int N, int K)
{
    int idx = blockIdx.x * 256 + threadIdx.x;
    int total = (N >> 3) * (K >> 3) * 32;
    if (idx >= total) return;
    int lane = idx & 31, t = idx >> 5;
    int KT = K >> 3;
    int kt = t % KT, nt = t / KT;
    int g = lane >> 2, tg = lane & 3;
    size_t r0 = (size_t)(nt * 8 + g) * K + kt * 8 + tg;
    uint2 v;
    v.x = f2tf32(W[r0]);
    v.y = f2tf32(W[r0 + 4]);
    ((uint2*)Wp)[(size_t)t * 32 + lane] = v;
}

// ---------------- persistent fragment-direct TF32 GEMM: C = A * W^T ------------
// Tile walk pairs CTAs (bid, bid+nsm) — co-resident on one SM — onto the same
// m-row, adjacent n-tiles, so A fragments are shared through L1.
__global__ __launch_bounds__(256, 2) void gemm_fp(
    const uint32_t* __restrict__ Apk, const uint32_t* __restrict__ Bp,
    float* __restrict__ C, int M, int N, int K, int nsm)
{
    int tid = threadIdx.x;
    int lane = tid & 31, wid = tid >> 5;
    int wm = wid & 1, wn = wid >> 1;
    int g = lane >> 2, tg = lane & 3;
    const int KT = K >> 3;
    const int ntn = N >> 7;
    const int ntiles = (M >> 7) * ntn;
    const size_t aStep = (size_t)KT * 32;
    const size_t bStep = (size_t)KT * 32;

    int smIdx = blockIdx.x % nsm;
    int slot  = blockIdx.x / nsm;     // 0 or 1 — pair members share an SM
    int stride = 2 * nsm;

    for (int k = 0;; k++) {
        int tIdx = k * stride + smIdx * 2 + slot;
        if (tIdx >= ntiles) break;
        int m0 = (tIdx / ntn) << 7;
        int n0 = (tIdx % ntn) << 7;

        const uint4* aP = (const uint4*)Apk + ((size_t)((m0 >> 4) + wm * 4) * KT) * 32 + lane;
        const uint2* bP = (const uint2*)Bp + ((size_t)((n0 >> 3) + wn * 4) * KT) * 32 + lane;

        float acc[4][4][4];
#pragma unroll
        for (int mf = 0; mf < 4; mf++)
#pragma unroll
            for (int nf = 0; nf < 4; nf++)
#pragma unroll
                for (int i = 0; i < 4; i++) acc[mf][nf][i] = 0.f;

#define LOADA(dst, kt) do { \
        _Pragma("unroll") \
        for (int mf = 0; mf < 4; mf++) { \
            uint4 u = aP[(size_t)mf * aStep + (size_t)(kt) * 32]; \
            dst[mf][0] = u.x; dst[mf][1] = u.y; dst[mf][2] = u.z; dst[mf][3] = u.w; \
        } \
    } while (0)
#define LOADB(dst, kt) do { \
        _Pragma("unroll") \
        for (int nf = 0; nf < 4; nf++) { \
            uint2 u = bP[(size_t)nf * bStep + (size_t)(kt) * 32]; \
            dst[nf][0] = u.x; dst[nf][1] = u.y; \
        } \
    } while (0)
#define DOMMA(a, b) do { \
        _Pragma("unroll") \
        for (int nf = 0; nf < 4; nf++) \
            _Pragma("unroll") \
            for (int mf = 0; mf < 4; mf++) \
                mma16n8k8(acc[mf][nf], a[mf], b[nf][0], b[nf][1]); \
    } while (0)

        uint32_t aA[4][4], aB[4][4], bA[4][2], bB[4][2];
        LOADA(aA, 0); LOADB(bA, 0);
        for (int kt = 0; kt < KT; kt += 2) {
            LOADA(aB, kt + 1); LOADB(bB, kt + 1);
            DOMMA(aA, bA);
            if (kt + 2 < KT) { LOADA(aA, kt + 2); LOADB(bA, kt + 2); }
            DOMMA(aB, bB);
        }
#undef LOADA
#undef LOADB
#undef DOMMA

#pragma unroll
        for (int mf = 0; mf < 4; mf++) {
            int r = m0 + wm * 64 + mf * 16 + g;
#pragma unroll
            for (int nf = 0; nf < 4; nf++) {
                int col = n0 + wn * 32 + nf * 8 + 2 * tg;
                float2 v0; v0.x = acc[mf][nf][0]; v0.y = acc[mf][nf][1];
                float2 v1; v1.x = acc[mf][nf][2]; v1.y = acc[mf][nf][3];
                *(float2*)(C + (size_t)r * N + col) = v0;
                *(float2*)(C + (size_t)(r + 8) * N + col) = v1;
            }
        }
    }
}

// ---------------- bf16 hi/lo fragment packing with fused RoPE ------------------
// Q: A-frags (m16k16), rope + scale.
__global__ __launch_bounds__(256) void pack_q(const float* __restrict__ QKV,
                                              uint4* __restrict__ Qpk)
{
    int idx = blockIdx.x * 256 + threadIdx.x;
    int lane = idx & 31, t = idx >> 5;
    int kc = t & 7; t >>= 3;
    int mt = t & 127; t >>= 7;
    int h = t & 31;
    int b = t >> 5;
    int g = lane >> 2, tg = lane & 3;
    const float scale = 0.08838834764831845f;
    const float ropeL = logf(10000.0f) / 64.0f;

    int c0 = kc * 16 + 2 * tg;
    int cp = c0 ^ 64;
    int s0 = mt * 16 + g;
    float sgn = (kc < 4) ? -1.f : 1.f;

    const float* base0 = QKV + (size_t)(b * SS + s0) * NQKV + h * HD;
    const float* base1 = base0 + (size_t)8 * NQKV;
    float2 a00 = *(const float2*)(base0 + c0);
    float2 a01 = *(const float2*)(base0 + c0 + 8);
    float2 p00 = *(const float2*)(base0 + cp);
    float2 p01 = *(const float2*)(base0 + cp + 8);
    float2 a10 = *(const float2*)(base1 + c0);
    float2 a11 = *(const float2*)(base1 + c0 + 8);
    float2 p10 = *(const float2*)(base1 + cp);
    float2 p11 = *(const float2*)(base1 + cp + 8);

    int jb = c0 & 63;
    float i0 = expf(-(float)jb * ropeL);
    float i1 = expf(-(float)(jb + 1) * ropeL);
    float i8 = expf(-(float)(jb + 8) * ropeL);
    float i9 = expf(-(float)(jb + 9) * ropeL);

    float sA = (float)s0, sB = (float)(s0 + 8);
    float v00x = (a00.x * cosf(sA * i0) + sgn * p00.x * sinf(sA * i0)) * scale;
    float v00y = (a00.y * cosf(sA * i1) + sgn * p00.y * sinf(sA * i1)) * scale;
    float v01x = (a01.x * cosf(sA * i8) + sgn * p01.x * sinf(sA * i8)) * scale;
    float v01y = (a01.y * cosf(sA * i9) + sgn * p01.y * sinf(sA * i9)) * scale;
    float v10x = (a10.x * cosf(sB * i0) + sgn * p10.x * sinf(sB * i0)) * scale;
    float v10y = (a10.y * cosf(sB * i1) + sgn * p10.y * sinf(sB * i1)) * scale;
    float v11x = (a11.x * cosf(sB * i8) + sgn * p11.x * sinf(sB * i8)) * scale;
    float v11y = (a11.y * cosf(sB * i9) + sgn * p11.y * sinf(sB * i9)) * scale;

    uint4 hi, lo;
    hi.x = bfpair(v00x, v00y); lo.x = bfpair_lo(v00x, v00y, hi.x);
    hi.y = bfpair(v10x, v10y); lo.y = bfpair_lo(v10x, v10y, hi.y);
    hi.z = bfpair(v01x, v01y); lo.z = bfpair_lo(v01x, v01y, hi.z);
    hi.w = bfpair(v11x, v11y); lo.w = bfpair_lo(v11x, v11y, hi.w);

    size_t o = ((((size_t)(b * 32 + h) * 128 + mt) * 8 + kc) * 64) + lane;
    Qpk[o] = hi;
    Qpk[o + 32] = lo;
}

// K: B-frags (n8k16) with fused rope.
__global__ __launch_bounds__(256) void pack_k(const float* __restrict__ QKV,
                                              uint4* __restrict__ Kpk)
{
    int idx = blockIdx.x * 256 + threadIdx.x;
    int lane = idx & 31, t = idx >> 5;
    int kc = t & 7; t >>= 3;
    int nt = t & 255; t >>= 8;
    int bkv = t;
    int b = bkv >> 3, kv = bkv & 7;
    int g = lane >> 2, tg = lane & 3;
    const float ropeL = logf(10000.0f) / 64.0f;

    int c0 = kc * 16 + 2 * tg;
    int cp = c0 ^ 64;
    int s0 = nt * 8 + g;
    float sgn = (kc < 4) ? -1.f : 1.f;

    const float* base = QKV + (size_t)(b * SS + s0) * NQKV + 4096 + kv * HD;
    float2 a0 = *(const float2*)(base + c0);
    float2 a1 = *(const float2*)(base + c0 + 8);
    float2 p0 = *(const float2*)(base + cp);
    float2 p1 = *(const float2*)(base + cp + 8);

    int jb = c0 & 63;
    float i0 = expf(-(float)jb * ropeL);
    float i1 = expf(-(float)(jb + 1) * ropeL);
    float i8 = expf(-(float)(jb + 8) * ropeL);
    float i9 = expf(-(float)(jb + 9) * ropeL);
    float s = (float)s0;

    float v0x = a0.x * cosf(s * i0) + sgn * p0.x * sinf(s * i0);
    float v0y = a0.y * cosf(s * i1) + sgn * p0.y * sinf(s * i1);
    float v1x = a1.x * cosf(s * i8) + sgn * p1.x * sinf(s * i8);
    float v1y = a1.y * cosf(s * i9) + sgn * p1.y * sinf(s * i9);

    uint4 o;
    o.x = bfpair(v0x, v0y);
    o.y = bfpair(v1x, v1y);
    o.z = bfpair_lo(v0x, v0y, o.x);
    o.w = bfpair_lo(v1x, v1y, o.y);
    Kpk[(((size_t)bkv * 256 + nt) * 8 + kc) * 32 + lane] = o;
}

// V^T: B-frags for PV (no rope).
__global__ __launch_bounds__(256) void pack_vt(const float* __restrict__ QKV,
                                               uint4* __restrict__ Vtp)
{
    int idx = blockIdx.x * 256 + threadIdx.x;
    int lane = idx & 31, t = idx >> 5;
    int kc = t & 3; t >>= 2;
    int nt = t & 15; t >>= 4;
    int vt = t & 31; t >>= 5;
    int bkv = t;
    int b = bkv >> 3, kv = bkv & 7;
    int g = lane >> 2, tg = lane & 3;

    int d = nt * 8 + g;
    int r0 = b * SS + vt * 64 + kc * 16 + 2 * tg;
    size_t col = 5120 + kv * HD + d;
    float x0 = QKV[(size_t)r0 * NQKV + col];
    float x1 = QKV[(size_t)(r0 + 1) * NQKV + col];
    float x2 = QKV[(size_t)(r0 + 8) * NQKV + col];
    float x3 = QKV[(size_t)(r0 + 9) * NQKV + col];
    uint4 o;
    o.x = bfpair(x0, x1);
    o.y = bfpair(x2, x3);
    o.z = bfpair_lo(x0, x1, o.x);
    o.w = bfpair_lo(x2, x3, o.y);
    Vtp[((((size_t)bkv * 32 + vt) * 16 + nt) * 4 + kc) * 32 + lane] = o;
}

// ---------------- Flash attention: fragment-direct, no CTA sync ----------------
#define VPITCH 72

__device__ __forceinline__ void split_store(__nv_bfloat16* dh, __nv_bfloat16* dl,
                                            float x0, float x1) {
    __nv_bfloat16 h0 = __float2bfloat16(x0);
    __nv_bfloat16 h1 = __float2bfloat16(x1);
    __nv_bfloat162 hv; hv.x = h0; hv.y = h1;
    __nv_bfloat162 lv;
    lv.x = __float2bfloat16(x0 - __bfloat162float(h0));
    lv.y = __float2bfloat16(x1 - __bfloat162float(h1));
    *(__nv_bfloat162*)dh = hv;
    *(__nv_bfloat162*)dl = lv;
}

__global__ __launch_bounds__(256, 1) void flash_mma(
    const uint4* __restrict__ Qpk, const uint4* __restrict__ Kpk,
    const uint4* __restrict__ Vtp, float* __restrict__ Aout)
{
    __shared__ __nv_bfloat16 Ph[128 * VPITCH];
    __shared__ __nv_bfloat16 Pl[128 * VPITCH];

    int tid = threadIdx.x, lane = tid & 31, wm = tid >> 5;
    int g = lane >> 2, tg = lane & 3;
    int qt = blockIdx.x, h = blockIdx.y, b = blockIdx.z;
    int bkv = b * NKV + (h >> 2);
    int q0 = qt * 128;
    const float NEGINF = __int_as_float(0xff800000);

    uint32_t qh[8][4], ql[8][4];
    {
        size_t qbase = (((size_t)(b * 32 + h) * 128 + qt * 8 + wm) * 8) * 64 + lane;
#pragma unroll
        for (int kc = 0; kc < 8; kc++) {
            uint4 hi = Qpk[qbase + (size_t)kc * 64];
            uint4 lo = Qpk[qbase + (size_t)kc * 64 + 32];
            qh[kc][0] = hi.x; qh[kc][1] = hi.y; qh[kc][2] = hi.z; qh[kc][3] = hi.w;
            ql[kc][0] = lo.x; ql[kc][1] = lo.y; ql[kc][2] = lo.z; ql[kc][3] = lo.w;
        }
    }

    float accO[16][4];
#pragma unroll
    for (int nf = 0; nf < 16; nf++)
#pragma unroll
        for (int i = 0; i < 4; i++) accO[nf][i] = 0.f;
    float m0 = NEGINF, m1 = NEGINF, l0 = 0.f, l1 = 0.f;

    const uint4* kBase = Kpk + ((size_t)bkv * 256) * 8 * 32 + lane;
    const uint4* vBase = Vtp + ((size_t)bkv * 32) * 16 * 4 * 32 + lane;

    int nkt = (q0 + wm * 16 + 15) / 64 + 1;
    for (int kt = 0; kt < nkt; kt++) {
        int k0g = kt * 64;
        float S[8][4];
#pragma unroll
        for (int nf = 0; nf < 8; nf++)
#pragma unroll
            for (int i = 0; i < 4; i++) S[nf][i] = 0.f;

#pragma unroll
        for (int kc = 0; kc < 8; kc++) {
#pragma unroll
            for (int nf = 0; nf < 8; nf++) {
                uint4 kk = kBase[(((size_t)(kt * 8 + nf)) * 8 + kc) * 32];
                mma_bf16(S[nf], qh[kc], kk.x, kk.y);
                mma_bf16(S[nf], qh[kc], kk.z, kk.w);
                mma_bf16(S[nf], ql[kc], kk.x, kk.y);
            }
        }
        if (k0g + 63 > q0 + wm * 16) {
            int row0 = q0 + wm * 16 + g, row1 = row0 + 8;
#pragma unroll
            for (int nf = 0; nf < 8; nf++) {
                int col = k0g + nf * 8 + 2 * tg;
                if (col     > row0) S[nf][0] = NEGINF;
                if (col + 1 > row0) S[nf][1] = NEGINF;
                if (col     > row1) S[nf][2] = NEGINF;
                if (col + 1 > row1) S[nf][3] = NEGINF;
            }
        }
        float mx0 = NEGINF, mx1 = NEGINF;
#pragma unroll
        for (int nf = 0; nf < 8; nf++) {
            mx0 = fmaxf(mx0, fmaxf(S[nf][0], S[nf][1]));
            mx1 = fmaxf(mx1, fmaxf(S[nf][2], S[nf][3]));
        }
        mx0 = fmaxf(mx0, __shfl_xor_sync(0xffffffff, mx0, 1));
        mx0 = fmaxf(mx0, __shfl_xor_sync(0xffffffff, mx0, 2));
        mx1 = fmaxf(mx1, __shfl_xor_sync(0xffffffff, mx1, 1));
        mx1 = fmaxf(mx1, __shfl_xor_sync(0xffffffff, mx1, 2));
        float m0n = fmaxf(m0, mx0), m1n = fmaxf(m1, mx1);
        float al0 = __expf(m0 - m0n), al1 = __expf(m1 - m1n);
        m0 = m0n; m1 = m1n;

        __syncwarp();
        float sum0 = 0.f, sum1 = 0.f;
        int pr0 = (wm * 16 + g) * VPITCH, pr1 = (wm * 16 + g + 8) * VPITCH;
#pragma unroll
        for (int nf = 0; nf < 8; nf++) {
            float p00 = __expf(S[nf][0] - m0);
            float p01 = __expf(S[nf][1] - m0);
            float p10 = __expf(S[nf][2] - m1);
            float p11 = __expf(S[nf][3] - m1);
            sum0 += p00 + p01;
            sum1 += p10 + p11;
            int co = nf * 8 + 2 * tg;
            split_store(Ph + pr0 + co, Pl + pr0 + co, p00, p01);
            split_store(Ph + pr1 + co, Pl + pr1 + co, p10, p11);
        }
        sum0 += __shfl_xor_sync(0xffffffff, sum0, 1);
        sum0 += __shfl_xor_sync(0xffffffff, sum0, 2);
        sum1 += __shfl_xor_sync(0xffffffff, sum1, 1);
        sum1 += __shfl_xor_sync(0xffffffff, sum1, 2);
        l0 = l0 * al0 + sum0;
        l1 = l1 * al1 + sum1;
#pragma unroll
        for (int nf = 0; nf < 16; nf++) {
            accO[nf][0] *= al0; accO[nf][1] *= al0;
            accO[nf][2] *= al1; accO[nf][3] *= al1;
        }
        __syncwarp();
#pragma unroll
        for (int kc = 0; kc < 4; kc++) {
            uint32_t pah[4], pal[4];
            const __nv_bfloat16* pb = Ph + (wm * 16 + g) * VPITCH + kc * 16 + 2 * tg;
            pah[0] = *(const uint32_t*)(pb);
            pah[1] = *(const uint32_t*)(pb + 8 * VPITCH);
            pah[2] = *(const uint32_t*)(pb + 8);
            pah[3] = *(const uint32_t*)(pb + 8 * VPITCH + 8);
            const __nv_bfloat16* pl = Pl + (wm * 16 + g) * VPITCH + kc * 16 + 2 * tg;
            pal[0] = *(const uint32_t*)(pl);
            pal[1] = *(const uint32_t*)(pl + 8 * VPITCH);
            pal[2] = *(const uint32_t*)(pl + 8);
            pal[3] = *(const uint32_t*)(pl + 8 * VPITCH + 8);
#pragma unroll
            for (int nf = 0; nf < 16; nf++) {
                uint4 vv = vBase[((((size_t)kt * 16 + nf) * 4) + kc) * 32];
                mma_bf16(accO[nf], pah, vv.x, vv.y);
                mma_bf16(accO[nf], pah, vv.z, vv.w);
                mma_bf16(accO[nf], pal, vv.x, vv.y);
            }
        }
    }

    float i0 = 1.0f / l0, i1 = 1.0f / l1;
    int r0 = q0 + wm * 16 + g;
    float* o0 = Aout + (((size_t)b * SS + r0) * NH + h) * HD;
    float* o1 = o0 + (size_t)8 * NH * HD;
#pragma unroll
    for (int nf = 0; nf < 16; nf++) {
        int d = nf * 8 + 2 * tg;
        float2 v0; v0.x = accO[nf][0] * i0; v0.y = accO[nf][1] * i0;
        float2 v1; v1.x = accO[nf][2] * i1; v1.y = accO[nf][3] * i1;
        *(float2*)(o0 + d) = v0;
        *(float2*)(o1 + d) = v1;
    }
}

// ---------------- launch --------------------------------------------------------
extern "C" void kernel_launch(void* const* d_in, const int* in_sizes, int n_in,
                              void* d_out, int out_size)
{
    const float* x  = (const float*)d_in[0];
    const float* wq = (const float*)d_in[1];
    const float* wk = (const float*)d_in[2];
    const float* wv = (const float*)d_in[3];
    const float* wo = (const float*)d_in[4];
    float* out = (float*)d_out;

    float *QKV, *Ap;
    uint32_t *Xp, *Apk, *Wqkvp, *Wop;
    uint4 *Qpk, *Kpk, *Vtp;
    cudaGetSymbolAddress((void**)&QKV, g_QKV);
    cudaGetSymbolAddress((void**)&Ap, g_A);
    cudaGetSymbolAddress((void**)&Xp, g_Xp);
    cudaGetSymbolAddress((void**)&Apk, g_Apk);
    cudaGetSymbolAddress((void**)&Wqkvp, g_Wqkvp);
    cudaGetSymbolAddress((void**)&Wop, g_Wop);
    cudaGetSymbolAddress((void**)&Qpk, g_Qpk);
    cudaGetSymbolAddress((void**)&Kpk, g_Kpk);
    cudaGetSymbolAddress((void**)&Vtp, g_Vtp);

    int smcount = 148;
    cudaDeviceGetAttribute(&smcount, cudaDevAttrMultiProcessorCount, 0);
    int pgrid = 2 * smcount;

    const int KT = HIDDEN / 8;   // 512

    // pack GEMM operands
    pack_a<<<(MROWS/16)*(HIDDEN/8)*32/256, 256>>>(x, Xp, MROWS, HIDDEN);
    pack_b<<<((NH*HD)/8)*KT*32/256, 256>>>(wq, Wqkvp, NH*HD, HIDDEN);
    pack_b<<<((NKV*HD)/8)*KT*32/256, 256>>>(wk, Wqkvp + (size_t)512*KT*32*2, NKV*HD, HIDDEN);
    pack_b<<<((NKV*HD)/8)*KT*32/256, 256>>>(wv, Wqkvp + (size_t)640*KT*32*2, NKV*HD, HIDDEN);

    // fused QKV projection (persistent, SM-paired tile walk)
    gemm_fp<<<pgrid, 256>>>(Xp, Wqkvp, QKV, MROWS, NQKV, HIDDEN, smcount);

    // bf16 hi/lo fragment packs (RoPE fused)
    pack_q<<<BB*NH*128*8*32/256, 256>>>(QKV, Qpk);
    pack_k<<<BB*NKV*256*8*32/256, 256>>>(QKV, Kpk);
    pack_vt<<<BB*NKV*32*16*4*32/256, 256>>>(QKV, Vtp);

    // flash attention
    flash_mma<<<dim3(SS/128, NH, BB), 256>>>(Qpk, Kpk, Vtp, Ap);

    // output projection
    pack_b<<<(HIDDEN/8)*((NH*HD)/8)*32/256, 256>>>(wo, Wop, HIDDEN, NH*HD);
    pack_a<<<(MROWS/16)*((NH*HD)/8)*32/256, 256>>>(Ap, Apk, MROWS, NH*HD);
    gemm_fp<<<pgrid, 256>>>(Apk, Wop, out, MROWS, HIDDEN, NH*HD, smcount);
}

// round 13
// speedup vs baseline: 1.0221x; 1.0221x over previous
#include <cuda_runtime.h>
#include <cuda_bf16.h>
#include <math.h>
#include <stdint.h>

#define HIDDEN 4096
#define NH 32
#define NKV 8
#define HD 128
#define BB 2
#define SS 2048
#define MROWS (BB*SS)   /* 4096 */
#define NQKV 6144       /* 4096 + 1024 + 1024 */

// ---------------- scratch -----------------------------------------------------
__device__ float g_QKV[(size_t)MROWS * NQKV];
__device__ float g_A[(size_t)MROWS * NH * HD];
__device__ uint32_t g_Xp   [(size_t)MROWS * HIDDEN];
__device__ uint32_t g_Apk  [(size_t)MROWS * NH * HD];
__device__ uint32_t g_Wqkvp[(size_t)NQKV * HIDDEN];
__device__ uint32_t g_Wop  [(size_t)HIDDEN * NH * HD];
__device__ uint4 g_Qpk[(size_t)BB * NH * 128 * 8 * 64];
__device__ uint4 g_Kpk[(size_t)BB * NKV * 256 * 8 * 32];
__device__ uint4 g_Vtp[(size_t)BB * NKV * 32 * 16 * 4 * 32];

__device__ __forceinline__ uint32_t f2tf32(float f) {
    uint32_t r; asm("cvt.rna.tf32.f32 %0, %1;" : "=r"(r) : "f"(f)); return r;
}
__device__ __forceinline__ uint32_t bfpair(float x0, float x1) {
    __nv_bfloat162 h; h.x = __float2bfloat16(x0); h.y = __float2bfloat16(x1);
    return *(uint32_t*)&h;
}
__device__ __forceinline__ uint32_t bfpair_lo(float x0, float x1, uint32_t hi) {
    __nv_bfloat162 h = *(__nv_bfloat162*)&hi;
    return bfpair(x0 - __bfloat162float(h.x), x1 - __bfloat162float(h.y));
}

__device__ __forceinline__ void mma16n8k8(float* d, const uint32_t* a,
                                          uint32_t b0, uint32_t b1) {
    asm volatile(
        "mma.sync.aligned.m16n8k8.row.col.f32.tf32.tf32.f32 "
        "{%0,%1,%2,%3}, {%4,%5,%6,%7}, {%8,%9}, {%0,%1,%2,%3};"
        : "+f"(d[0]), "+f"(d[1]), "+f"(d[2]), "+f"(d[3])
        : "r"(a[0]), "r"(a[1]), "r"(a[2]), "r"(a[3]), "r"(b0), "r"(b1));
}
__device__ __forceinline__ void mma_bf16(float* d, const uint32_t* a,
                                         uint32_t b0, uint32_t b1) {
    asm volatile(
        "mma.sync.aligned.m16n8k16.row.col.f32.bf16.bf16.f32 "
        "{%0,%1,%2,%3}, {%4,%5,%6,%7}, {%8,%9}, {%0,%1,%2,%3};"
        : "+f"(d[0]), "+f"(d[1]), "+f"(d[2]), "+f"(d[3])
        : "r"(a[0]), "r"(a[1]), "r"(a[2]), "r"(a[3]), "r"(b0), "r"(b1));
}

// ---------------- tf32 packing (GEMM operands) ---------------------------------
__global__ __launch_bounds__(256) void pack_a(const float* __restrict__ X,
                                              uint32_t* __restrict__ Xp,
                                              int M, int K)
{
    int idx = blockIdx.x * 256 + threadIdx.x;
    int total = (M >> 4) * (K >> 3) * 32;
    if (idx >= total) return;
    int lane = idx & 31, t = idx >> 5;
    int KT = K >> 3;
    int kt = t % KT, mt = t / KT;
    int g = lane >> 2, tg = lane & 3;
    size_t r0 = (size_t)(mt * 16 + g) * K + kt * 8 + tg;
    uint4 v;
    v.x = f2tf32(X[r0]);
    v.y = f2tf32(X[r0 + (size_t)8 * K]);
    v.z = f2tf32(X[r0 + 4]);
    v.w = f2tf32(X[r0 + (size_t)8 * K + 4]);
    ((uint4*)Xp)[(size_t)t * 32 + lane] = v;
}

__global__ __launch_bounds__(256) void pack_b(const float* __restrict__ W,
                                              uint32_t* __restrict__ Wp,
                                              int N, int K)
{
    int idx = blockIdx.x * 256 + threadIdx.x;
    int total = (N >> 3) * (K >> 3) * 32;
    if (idx >= total) return;
    int lane = idx & 31, t = idx >> 5;
    int KT = K >> 3;
    int kt = t % KT, nt = t / KT;
    int g = lane >> 2, tg = lane & 3;
    size_t r0 = (size_t)(nt * 8 + g) * K + kt * 8 + tg;
    uint2 v;
    v.x = f2tf32(W[r0]);
    v.y = f2tf32(W[r0 + 4]);
    ((uint2*)Wp)[(size_t)t * 32 + lane] = v;
}

// ---------------- persistent fragment-direct TF32 GEMM: C = A * W^T ------------
// Banded tile walk: n processed in bands of 8 n-tiles (1024 cols) so the B band
// (16 MB) stays L2-resident across the whole m sweep; B hits DRAM only once.
__global__ __launch_bounds__(256, 2) void gemm_fp(
    const uint32_t* __restrict__ Apk, const uint32_t* __restrict__ Bp,
    float* __restrict__ C, int M, int N, int K)
{
    int tid = threadIdx.x;
    int lane = tid & 31, wid = tid >> 5;
    int wm = wid & 1, wn = wid >> 1;
    int g = lane >> 2, tg = lane & 3;
    const int KT = K >> 3;
    const int ntn = N >> 7;
    const int ntm = M >> 7;
    const int ntiles = ntm * ntn;
    const int BAND = 8;                 // ntn (48, 32) divisible by 8
    const int perBand = ntm * BAND;
    const size_t aStep = (size_t)KT * 32;
    const size_t bStep = (size_t)KT * 32;

    for (int tIdx = blockIdx.x; tIdx < ntiles; tIdx += gridDim.x) {
        int bi = tIdx / perBand;
        int r  = tIdx % perBand;
        int m0 = (r / BAND) << 7;
        int n0 = (bi * BAND + (r % BAND)) << 7;

        const uint4* aP = (const uint4*)Apk + ((size_t)((m0 >> 4) + wm * 4) * KT) * 32 + lane;
        const uint2* bP = (const uint2*)Bp + ((size_t)((n0 >> 3) + wn * 4) * KT) * 32 + lane;

        float acc[4][4][4];
#pragma unroll
        for (int mf = 0; mf < 4; mf++)
#pragma unroll
            for (int nf = 0; nf < 4; nf++)
#pragma unroll
                for (int i = 0; i < 4; i++) acc[mf][nf][i] = 0.f;

#define LOADA(dst, kt) do { \
        _Pragma("unroll") \
        for (int mf = 0; mf < 4; mf++) { \
            uint4 u = aP[(size_t)mf * aStep + (size_t)(kt) * 32]; \
            dst[mf][0] = u.x; dst[mf][1] = u.y; dst[mf][2] = u.z; dst[mf][3] = u.w; \
        } \
    } while (0)
#define LOADB(dst, kt) do { \
        _Pragma("unroll") \
        for (int nf = 0; nf < 4; nf++) { \
            uint2 u = bP[(size_t)nf * bStep + (size_t)(kt) * 32]; \
            dst[nf][0] = u.x; dst[nf][1] = u.y; \
        } \
    } while (0)
#define DOMMA(a, b) do { \
        _Pragma("unroll") \
        for (int nf = 0; nf < 4; nf++) \
            _Pragma("unroll") \
            for (int mf = 0; mf < 4; mf++) \
                mma16n8k8(acc[mf][nf], a[mf], b[nf][0], b[nf][1]); \
    } while (0)

        uint32_t aA[4][4], aB[4][4], bA[4][2], bB[4][2];
        LOADA(aA, 0); LOADB(bA, 0);
        for (int kt = 0; kt < KT; kt += 2) {
            LOADA(aB, kt + 1); LOADB(bB, kt + 1);
            DOMMA(aA, bA);
            if (kt + 2 < KT) { LOADA(aA, kt + 2); LOADB(bA, kt + 2); }
            DOMMA(aB, bB);
        }
#undef LOADA
#undef LOADB
#undef DOMMA

#pragma unroll
        for (int mf = 0; mf < 4; mf++) {
            int rr = m0 + wm * 64 + mf * 16 + g;
#pragma unroll
            for (int nf = 0; nf < 4; nf++) {
                int col = n0 + wn * 32 + nf * 8 + 2 * tg;
                float2 v0; v0.x = acc[mf][nf][0]; v0.y = acc[mf][nf][1];
                float2 v1; v1.x = acc[mf][nf][2]; v1.y = acc[mf][nf][3];
                *(float2*)(C + (size_t)rr * N + col) = v0;
                *(float2*)(C + (size_t)(rr + 8) * N + col) = v1;
            }
        }
    }
}

// ---------------- bf16 hi/lo fragment packing with fused RoPE ------------------
__global__ __launch_bounds__(256) void pack_q(const float* __restrict__ QKV,
                                              uint4* __restrict__ Qpk)
{
    int idx = blockIdx.x * 256 + threadIdx.x;
    int lane = idx & 31, t = idx >> 5;
    int kc = t & 7; t >>= 3;
    int mt = t & 127; t >>= 7;
    int h = t & 31;
    int b = t >> 5;
    int g = lane >> 2, tg = lane & 3;
    const float scale = 0.08838834764831845f;
    const float ropeL = logf(10000.0f) / 64.0f;

    int c0 = kc * 16 + 2 * tg;
    int cp = c0 ^ 64;
    int s0 = mt * 16 + g;
    float sgn = (kc < 4) ? -1.f : 1.f;

    const float* base0 = QKV + (size_t)(b * SS + s0) * NQKV + h * HD;
    const float* base1 = base0 + (size_t)8 * NQKV;
    float2 a00 = *(const float2*)(base0 + c0);
    float2 a01 = *(const float2*)(base0 + c0 + 8);
    float2 p00 = *(const float2*)(base0 + cp);
    float2 p01 = *(const float2*)(base0 + cp + 8);
    float2 a10 = *(const float2*)(base1 + c0);
    float2 a11 = *(const float2*)(base1 + c0 + 8);
    float2 p10 = *(const float2*)(base1 + cp);
    float2 p11 = *(const float2*)(base1 + cp + 8);

    int jb = c0 & 63;
    float i0 = expf(-(float)jb * ropeL);
    float i1 = expf(-(float)(jb + 1) * ropeL);
    float i8 = expf(-(float)(jb + 8) * ropeL);
    float i9 = expf(-(float)(jb + 9) * ropeL);

    float sA = (float)s0, sB = (float)(s0 + 8);
    float v00x = (a00.x * cosf(sA * i0) + sgn * p00.x * sinf(sA * i0)) * scale;
    float v00y = (a00.y * cosf(sA * i1) + sgn * p00.y * sinf(sA * i1)) * scale;
    float v01x = (a01.x * cosf(sA * i8) + sgn * p01.x * sinf(sA * i8)) * scale;
    float v01y = (a01.y * cosf(sA * i9) + sgn * p01.y * sinf(sA * i9)) * scale;
    float v10x = (a10.x * cosf(sB * i0) + sgn * p10.x * sinf(sB * i0)) * scale;
    float v10y = (a10.y * cosf(sB * i1) + sgn * p10.y * sinf(sB * i1)) * scale;
    float v11x = (a11.x * cosf(sB * i8) + sgn * p11.x * sinf(sB * i8)) * scale;
    float v11y = (a11.y * cosf(sB * i9) + sgn * p11.y * sinf(sB * i9)) * scale;

    uint4 hi, lo;
    hi.x = bfpair(v00x, v00y); lo.x = bfpair_lo(v00x, v00y, hi.x);
    hi.y = bfpair(v10x, v10y); lo.y = bfpair_lo(v10x, v10y, hi.y);
    hi.z = bfpair(v01x, v01y); lo.z = bfpair_lo(v01x, v01y, hi.z);
    hi.w = bfpair(v11x, v11y); lo.w = bfpair_lo(v11x, v11y, hi.w);

    size_t o = ((((size_t)(b * 32 + h) * 128 + mt) * 8 + kc) * 64) + lane;
    Qpk[o] = hi;
    Qpk[o + 32] = lo;
}

__global__ __launch_bounds__(256) void pack_k(const float* __restrict__ QKV,
                                              uint4* __restrict__ Kpk)
{
    int idx = blockIdx.x * 256 + threadIdx.x;
    int lane = idx & 31, t = idx >> 5;
    int kc = t & 7; t >>= 3;
    int nt = t & 255; t >>= 8;
    int bkv = t;
    int b = bkv >> 3, kv = bkv & 7;
    int g = lane >> 2, tg = lane & 3;
    const float ropeL = logf(10000.0f) / 64.0f;

    int c0 = kc * 16 + 2 * tg;
    int cp = c0 ^ 64;
    int s0 = nt * 8 + g;
    float sgn = (kc < 4) ? -1.f : 1.f;

    const float* base = QKV + (size_t)(b * SS + s0) * NQKV + 4096 + kv * HD;
    float2 a0 = *(const float2*)(base + c0);
    float2 a1 = *(const float2*)(base + c0 + 8);
    float2 p0 = *(const float2*)(base + cp);
    float2 p1 = *(const float2*)(base + cp + 8);

    int jb = c0 & 63;
    float i0 = expf(-(float)jb * ropeL);
    float i1 = expf(-(float)(jb + 1) * ropeL);
    float i8 = expf(-(float)(jb + 8) * ropeL);
    float i9 = expf(-(float)(jb + 9) * ropeL);
    float s = (float)s0;

    float v0x = a0.x * cosf(s * i0) + sgn * p0.x * sinf(s * i0);
    float v0y = a0.y * cosf(s * i1) + sgn * p0.y * sinf(s * i1);
    float v1x = a1.x * cosf(s * i8) + sgn * p1.x * sinf(s * i8);
    float v1y = a1.y * cosf(s * i9) + sgn * p1.y * sinf(s * i9);

    uint4 o;
    o.x = bfpair(v0x, v0y);
    o.y = bfpair(v1x, v1y);
    o.z = bfpair_lo(v0x, v0y, o.x);
    o.w = bfpair_lo(v1x, v1y, o.y);
    Kpk[(((size_t)bkv * 256 + nt) * 8 + kc) * 32 + lane] = o;
}

__global__ __launch_bounds__(256) void pack_vt(const float* __restrict__ QKV,
                                               uint4* __restrict__ Vtp)
{
    int idx = blockIdx.x * 256 + threadIdx.x;
    int lane = idx & 31, t = idx >> 5;
    int kc = t & 3; t >>= 2;
    int nt = t & 15; t >>= 4;
    int vt = t & 31; t >>= 5;
    int bkv = t;
    int b = bkv >> 3, kv = bkv & 7;
    int g = lane >> 2, tg = lane & 3;

    int d = nt * 8 + g;
    int r0 = b * SS + vt * 64 + kc * 16 + 2 * tg;
    size_t col = 5120 + kv * HD + d;
    float x0 = QKV[(size_t)r0 * NQKV + col];
    float x1 = QKV[(size_t)(r0 + 1) * NQKV + col];
    float x2 = QKV[(size_t)(r0 + 8) * NQKV + col];
    float x3 = QKV[(size_t)(r0 + 9) * NQKV + col];
    uint4 o;
    o.x = bfpair(x0, x1);
    o.y = bfpair(x2, x3);
    o.z = bfpair_lo(x0, x1, o.x);
    o.w = bfpair_lo(x2, x3, o.y);
    Vtp[((((size_t)bkv * 32 + vt) * 16 + nt) * 4 + kc) * 32 + lane] = o;
}

// ---------------- Flash attention: fragment-direct, no CTA sync ----------------
#define VPITCH 72

__device__ __forceinline__ void split_store(__nv_bfloat16* dh, __nv_bfloat16* dl,
                                            float x0, float x1) {
    __nv_bfloat16 h0 = __float2bfloat16(x0);
    __nv_bfloat16 h1 = __float2bfloat16(x1);
    __nv_bfloat162 hv; hv.x = h0; hv.y = h1;
    __nv_bfloat162 lv;
    lv.x = __float2bfloat16(x0 - __bfloat162float(h0));
    lv.y = __float2bfloat16(x1 - __bfloat162float(h1));
    *(__nv_bfloat162*)dh = hv;
    *(__nv_bfloat162*)dl = lv;
}

__global__ __launch_bounds__(256, 1) void flash_mma(
    const uint4* __restrict__ Qpk, const uint4* __restrict__ Kpk,
    const uint4* __restrict__ Vtp, float* __restrict__ Aout)
{
    __shared__ __nv_bfloat16 Ph[128 * VPITCH];
    __shared__ __nv_bfloat16 Pl[128 * VPITCH];

    int tid = threadIdx.x, lane = tid & 31, wm = tid >> 5;
    int g = lane >> 2, tg = lane & 3;
    int qt = blockIdx.x, h = blockIdx.y, b = blockIdx.z;
    int bkv = b * NKV + (h >> 2);
    int q0 = qt * 128;
    const float NEGINF = __int_as_float(0xff800000);

    uint32_t qh[8][4], ql[8][4];
    {
        size_t qbase = (((size_t)(b * 32 + h) * 128 + qt * 8 + wm) * 8) * 64 + lane;
#pragma unroll
        for (int kc = 0; kc < 8; kc++) {
            uint4 hi = Qpk[qbase + (size_t)kc * 64];
            uint4 lo = Qpk[qbase + (size_t)kc * 64 + 32];
            qh[kc][0] = hi.x; qh[kc][1] = hi.y; qh[kc][2] = hi.z; qh[kc][3] = hi.w;
            ql[kc][0] = lo.x; ql[kc][1] = lo.y; ql[kc][2] = lo.z; ql[kc][3] = lo.w;
        }
    }

    float accO[16][4];
#pragma unroll
    for (int nf = 0; nf < 16; nf++)
#pragma unroll
        for (int i = 0; i < 4; i++) accO[nf][i] = 0.f;
    float m0 = NEGINF, m1 = NEGINF, l0 = 0.f, l1 = 0.f;

    const uint4* kBase = Kpk + ((size_t)bkv * 256) * 8 * 32 + lane;
    const uint4* vBase = Vtp + ((size_t)bkv * 32) * 16 * 4 * 32 + lane;

    int nkt = (q0 + wm * 16 + 15) / 64 + 1;
    for (int kt = 0; kt < nkt; kt++) {
        int k0g = kt * 64;
        float S[8][4];
#pragma unroll
        for (int nf = 0; nf < 8; nf++)
#pragma unroll
            for (int i = 0; i < 4; i++) S[nf][i] = 0.f;

#pragma unroll
        for (int kc = 0; kc < 8; kc++) {
#pragma unroll
            for (int nf = 0; nf < 8; nf++) {
                uint4 kk = kBase[(((size_t)(kt * 8 + nf)) * 8 + kc) * 32];
                mma_bf16(S[nf], qh[kc], kk.x, kk.y);
                mma_bf16(S[nf], qh[kc], kk.z, kk.w);
                mma_bf16(S[nf], ql[kc], kk.x, kk.y);
            }
        }
        if (k0g + 63 > q0 + wm * 16) {
            int row0 = q0 + wm * 16 + g, row1 = row0 + 8;
#pragma unroll
            for (int nf = 0; nf < 8; nf++) {
                int col = k0g + nf * 8 + 2 * tg;
                if (col     > row0) S[nf][0] = NEGINF;
                if (col + 1 > row0) S[nf][1] = NEGINF;
                if (col     > row1) S[nf][2] = NEGINF;
                if (col + 1 > row1) S[nf][3] = NEGINF;
            }
        }
        float mx0 = NEGINF, mx1 = NEGINF;
#pragma unroll
        for (int nf = 0; nf < 8; nf++) {
            mx0 = fmaxf(mx0, fmaxf(S[nf][0], S[nf][1]));
            mx1 = fmaxf(mx1, fmaxf(S[nf][2], S[nf][3]));
        }
        mx0 = fmaxf(mx0, __shfl_xor_sync(0xffffffff, mx0, 1));
        mx0 = fmaxf(mx0, __shfl_xor_sync(0xffffffff, mx0, 2));
        mx1 = fmaxf(mx1, __shfl_xor_sync(0xffffffff, mx1, 1));
        mx1 = fmaxf(mx1, __shfl_xor_sync(0xffffffff, mx1, 2));
        float m0n = fmaxf(m0, mx0), m1n = fmaxf(m1, mx1);
        float al0 = __expf(m0 - m0n), al1 = __expf(m1 - m1n);
        m0 = m0n; m1 = m1n;

        __syncwarp();
        float sum0 = 0.f, sum1 = 0.f;
        int pr0 = (wm * 16 + g) * VPITCH, pr1 = (wm * 16 + g + 8) * VPITCH;
#pragma unroll
        for (int nf = 0; nf < 8; nf++) {
            float p00 = __expf(S[nf][0] - m0);
            float p01 = __expf(S[nf][1] - m0);
            float p10 = __expf(S[nf][2] - m1);
            float p11 = __expf(S[nf][3] - m1);
            sum0 += p00 + p01;
            sum1 += p10 + p11;
            int co = nf * 8 + 2 * tg;
            split_store(Ph + pr0 + co, Pl + pr0 + co, p00, p01);
            split_store(Ph + pr1 + co, Pl + pr1 + co, p10, p11);
        }
        sum0 += __shfl_xor_sync(0xffffffff, sum0, 1);
        sum0 += __shfl_xor_sync(0xffffffff, sum0, 2);
        sum1 += __shfl_xor_sync(0xffffffff, sum1, 1);
        sum1 += __shfl_xor_sync(0xffffffff, sum1, 2);
        l0 = l0 * al0 + sum0;
        l1 = l1 * al1 + sum1;
#pragma unroll
        for (int nf = 0; nf < 16; nf++) {
            accO[nf][0] *= al0; accO[nf][1] *= al0;
            accO[nf][2] *= al1; accO[nf][3] *= al1;
        }
        __syncwarp();
#pragma unroll
        for (int kc = 0; kc < 4; kc++) {
            uint32_t pah[4], pal[4];
            const __nv_bfloat16* pb = Ph + (wm * 16 + g) * VPITCH + kc * 16 + 2 * tg;
            pah[0] = *(const uint32_t*)(pb);
            pah[1] = *(const uint32_t*)(pb + 8 * VPITCH);
            pah[2] = *(const uint32_t*)(pb + 8);
            pah[3] = *(const uint32_t*)(pb + 8 * VPITCH + 8);
            const __nv_bfloat16* pl = Pl + (wm * 16 + g) * VPITCH + kc * 16 + 2 * tg;
            pal[0] = *(const uint32_t*)(pl);
            pal[1] = *(const uint32_t*)(pl + 8 * VPITCH);
            pal[2] = *(const uint32_t*)(pl + 8);
            pal[3] = *(const uint32_t*)(pl + 8 * VPITCH + 8);
#pragma unroll
            for (int nf = 0; nf < 16; nf++) {
                uint4 vv = vBase[((((size_t)kt * 16 + nf) * 4) + kc) * 32];
                mma_bf16(accO[nf], pah, vv.x, vv.y);
                mma_bf16(accO[nf], pah, vv.z, vv.w);
                mma_bf16(accO[nf], pal, vv.x, vv.y);
            }
        }
    }

    float i0 = 1.0f / l0, i1 = 1.0f / l1;
    int r0 = q0 + wm * 16 + g;
    float* o0 = Aout + (((size_t)b * SS + r0) * NH + h) * HD;
    float* o1 = o0 + (size_t)8 * NH * HD;
#pragma unroll
    for (int nf = 0; nf < 16; nf++) {
        int d = nf * 8 + 2 * tg;
        float2 v0; v0.x = accO[nf][0] * i0; v0.y = accO[nf][1] * i0;
        float2 v1; v1.x = accO[nf][2] * i1; v1.y = accO[nf][3] * i1;
        *(float2*)(o0 + d) = v0;
        *(float2*)(o1 + d) = v1;
    }
}

// ---------------- launch --------------------------------------------------------
extern "C" void kernel_launch(void* const* d_in, const int* in_sizes, int n_in,
                              void* d_out, int out_size)
{
    const float* x  = (const float*)d_in[0];
    const float* wq = (const float*)d_in[1];
    const float* wk = (const float*)d_in[2];
    const float* wv = (const float*)d_in[3];
    const float* wo = (const float*)d_in[4];
    float* out = (float*)d_out;

    float *QKV, *Ap;
    uint32_t *Xp, *Apk, *Wqkvp, *Wop;
    uint4 *Qpk, *Kpk, *Vtp;
    cudaGetSymbolAddress((void**)&QKV, g_QKV);
    cudaGetSymbolAddress((void**)&Ap, g_A);
    cudaGetSymbolAddress((void**)&Xp, g_Xp);
    cudaGetSymbolAddress((void**)&Apk, g_Apk);
    cudaGetSymbolAddress((void**)&Wqkvp, g_Wqkvp);
    cudaGetSymbolAddress((void**)&Wop, g_Wop);
    cudaGetSymbolAddress((void**)&Qpk, g_Qpk);
    cudaGetSymbolAddress((void**)&Kpk, g_Kpk);
    cudaGetSymbolAddress((void**)&Vtp, g_Vtp);

    int smcount = 148;
    cudaDeviceGetAttribute(&smcount, cudaDevAttrMultiProcessorCount, 0);
    int pgrid = 2 * smcount;

    const int KT = HIDDEN / 8;   // 512

    // pack GEMM operands
    pack_a<<<(MROWS/16)*(HIDDEN/8)*32/256, 256>>>(x, Xp, MROWS, HIDDEN);
    pack_b<<<((NH*HD)/8)*KT*32/256, 256>>>(wq, Wqkvp, NH*HD, HIDDEN);
    pack_b<<<((NKV*HD)/8)*KT*32/256, 256>>>(wk, Wqkvp + (size_t)512*KT*32*2, NKV*HD, HIDDEN);
    pack_b<<<((NKV*HD)/8)*KT*32/256, 256>>>(wv, Wqkvp + (size_t)640*KT*32*2, NKV*HD, HIDDEN);

    // fused QKV projection (persistent, banded walk)
    gemm_fp<<<pgrid, 256>>>(Xp, Wqkvp, QKV, MROWS, NQKV, HIDDEN);

    // bf16 hi/lo fragment packs (RoPE fused)
    pack_q<<<BB*NH*128*8*32/256, 256>>>(QKV, Qpk);
    pack_k<<<BB*NKV*256*8*32/256, 256>>>(QKV, Kpk);
    pack_vt<<<BB*NKV*32*16*4*32/256, 256>>>(QKV, Vtp);

    // flash attention
    flash_mma<<<dim3(SS/128, NH, BB), 256>>>(Qpk, Kpk, Vtp, Ap);

    // output projection
    pack_b<<<(HIDDEN/8)*((NH*HD)/8)*32/256, 256>>>(wo, Wop, HIDDEN, NH*HD);
    pack_a<<<(MROWS/16)*((NH*HD)/8)*32/256, 256>>>(Ap, Apk, MROWS, NH*HD);
    gemm_fp<<<pgrid, 256>>>(Apk, Wop, out, MROWS, HIDDEN, NH*HD);
}

// round 14
// speedup vs baseline: 1.0607x; 1.0378x over previous
#include <cuda_runtime.h>
#include <cuda_bf16.h>
#include <math.h>
#include <stdint.h>

#define HIDDEN 4096
#define NH 32
#define NKV 8
#define HD 128
#define BB 2
#define SS 2048
#define MROWS (BB*SS)   /* 4096 */
#define NQKV 6144       /* 4096 + 1024 + 1024 */

// ---------------- scratch -----------------------------------------------------
__device__ float g_QKV[(size_t)MROWS * NQKV];
__device__ float g_A[(size_t)MROWS * NH * HD];
__device__ uint32_t g_Xp   [(size_t)MROWS * HIDDEN];
__device__ uint32_t g_Apk  [(size_t)MROWS * NH * HD];
__device__ uint32_t g_Wqkvp[(size_t)NQKV * HIDDEN];
__device__ uint32_t g_Wop  [(size_t)HIDDEN * NH * HD];
__device__ uint4 g_Qpk[(size_t)BB * NH * 128 * 8 * 64];
__device__ uint4 g_Kpk[(size_t)BB * NKV * 256 * 8 * 32];
__device__ uint4 g_Vtp[(size_t)BB * NKV * 32 * 16 * 4 * 32];

__device__ __forceinline__ uint32_t f2tf32(float f) {
    uint32_t r; asm("cvt.rna.tf32.f32 %0, %1;" : "=r"(r) : "f"(f)); return r;
}
__device__ __forceinline__ uint32_t bfpair(float x0, float x1) {
    __nv_bfloat162 h; h.x = __float2bfloat16(x0); h.y = __float2bfloat16(x1);
    return *(uint32_t*)&h;
}
__device__ __forceinline__ uint32_t bfpair_lo(float x0, float x1, uint32_t hi) {
    __nv_bfloat162 h = *(__nv_bfloat162*)&hi;
    return bfpair(x0 - __bfloat162float(h.x), x1 - __bfloat162float(h.y));
}

__device__ __forceinline__ void mma16n8k8(float* d, const uint32_t* a,
                                          uint32_t b0, uint32_t b1) {
    asm volatile(
        "mma.sync.aligned.m16n8k8.row.col.f32.tf32.tf32.f32 "
        "{%0,%1,%2,%3}, {%4,%5,%6,%7}, {%8,%9}, {%0,%1,%2,%3};"
        : "+f"(d[0]), "+f"(d[1]), "+f"(d[2]), "+f"(d[3])
        : "r"(a[0]), "r"(a[1]), "r"(a[2]), "r"(a[3]), "r"(b0), "r"(b1));
}
__device__ __forceinline__ void mma_bf16(float* d, const uint32_t* a,
                                         uint32_t b0, uint32_t b1) {
    asm volatile(
        "mma.sync.aligned.m16n8k16.row.col.f32.bf16.bf16.f32 "
        "{%0,%1,%2,%3}, {%4,%5,%6,%7}, {%8,%9}, {%0,%1,%2,%3};"
        : "+f"(d[0]), "+f"(d[1]), "+f"(d[2]), "+f"(d[3])
        : "r"(a[0]), "r"(a[1]), "r"(a[2]), "r"(a[3]), "r"(b0), "r"(b1));
}

// ---------------- tf32 packing (GEMM operands) ---------------------------------
__global__ __launch_bounds__(256) void pack_a(const float* __restrict__ X,
                                              uint32_t* __restrict__ Xp,
                                              int M, int K)
{
    int idx = blockIdx.x * 256 + threadIdx.x;
    int total = (M >> 4) * (K >> 3) * 32;
    if (idx >= total) return;
    int lane = idx & 31, t = idx >> 5;
    int KT = K >> 3;
    int kt = t % KT, mt = t / KT;
    int g = lane >> 2, tg = lane & 3;
    size_t r0 = (size_t)(mt * 16 + g) * K + kt * 8 + tg;
    uint4 v;
    v.x = f2tf32(X[r0]);
    v.y = f2tf32(X[r0 + (size_t)8 * K]);
    v.z = f2tf32(X[r0 + 4]);
    v.w = f2tf32(X[r0 + (size_t)8 * K + 4]);
    ((uint4*)Xp)[(size_t)t * 32 + lane] = v;
}

__global__ __launch_bounds__(256) void pack_b(const float* __restrict__ W,
                                              uint32_t* __restrict__ Wp,
                                              int N, int K)
{
    int idx = blockIdx.x * 256 + threadIdx.x;
    int total = (N >> 3) * (K >> 3) * 32;
    if (idx >= total) return;
    int lane = idx & 31, t = idx >> 5;
    int KT = K >> 3;
    int kt = t % KT, nt = t / KT;
    int g = lane >> 2, tg = lane & 3;
    size_t r0 = (size_t)(nt * 8 + g) * K + kt * 8 + tg;
    uint2 v;
    v.x = f2tf32(W[r0]);
    v.y = f2tf32(W[r0 + 4]);
    ((uint2*)Wp)[(size_t)t * 32 + lane] = v;
}

// ---------------- persistent fragment-direct TF32 GEMM: C = A * W^T ------------
__global__ __launch_bounds__(256, 2) void gemm_fp(
    const uint32_t* __restrict__ Apk, const uint32_t* __restrict__ Bp,
    float* __restrict__ C, int M, int N, int K)
{
    int tid = threadIdx.x;
    int lane = tid & 31, wid = tid >> 5;
    int wm = wid & 1, wn = wid >> 1;
    int g = lane >> 2, tg = lane & 3;
    const int KT = K >> 3;
    const int ntn = N >> 7;
    const int ntm = M >> 7;
    const int ntiles = ntm * ntn;
    const int BAND = 8;
    const int perBand = ntm * BAND;
    const size_t aStep = (size_t)KT * 32;
    const size_t bStep = (size_t)KT * 32;

    for (int tIdx = blockIdx.x; tIdx < ntiles; tIdx += gridDim.x) {
        int bi = tIdx / perBand;
        int r  = tIdx % perBand;
        int m0 = (r / BAND) << 7;
        int n0 = (bi * BAND + (r % BAND)) << 7;

        const uint4* aP = (const uint4*)Apk + ((size_t)((m0 >> 4) + wm * 4) * KT) * 32 + lane;
        const uint2* bP = (const uint2*)Bp + ((size_t)((n0 >> 3) + wn * 4) * KT) * 32 + lane;

        float acc[4][4][4];
#pragma unroll
        for (int mf = 0; mf < 4; mf++)
#pragma unroll
            for (int nf = 0; nf < 4; nf++)
#pragma unroll
                for (int i = 0; i < 4; i++) acc[mf][nf][i] = 0.f;

#define LOADA(dst, kt) do { \
        _Pragma("unroll") \
        for (int mf = 0; mf < 4; mf++) { \
            uint4 u = aP[(size_t)mf * aStep + (size_t)(kt) * 32]; \
            dst[mf][0] = u.x; dst[mf][1] = u.y; dst[mf][2] = u.z; dst[mf][3] = u.w; \
        } \
    } while (0)
#define LOADB(dst, kt) do { \
        _Pragma("unroll") \
        for (int nf = 0; nf < 4; nf++) { \
            uint2 u = bP[(size_t)nf * bStep + (size_t)(kt) * 32]; \
            dst[nf][0] = u.x; dst[nf][1] = u.y; \
        } \
    } while (0)
#define DOMMA(a, b) do { \
        _Pragma("unroll") \
        for (int nf = 0; nf < 4; nf++) \
            _Pragma("unroll") \
            for (int mf = 0; mf < 4; mf++) \
                mma16n8k8(acc[mf][nf], a[mf], b[nf][0], b[nf][1]); \
    } while (0)

        uint32_t aA[4][4], aB[4][4], bA[4][2], bB[4][2];
        LOADA(aA, 0); LOADB(bA, 0);
        for (int kt = 0; kt < KT; kt += 2) {
            LOADA(aB, kt + 1); LOADB(bB, kt + 1);
            DOMMA(aA, bA);
            if (kt + 2 < KT) { LOADA(aA, kt + 2); LOADB(bA, kt + 2); }
            DOMMA(aB, bB);
        }
#undef LOADA
#undef LOADB
#undef DOMMA

#pragma unroll
        for (int mf = 0; mf < 4; mf++) {
            int rr = m0 + wm * 64 + mf * 16 + g;
#pragma unroll
            for (int nf = 0; nf < 4; nf++) {
                int col = n0 + wn * 32 + nf * 8 + 2 * tg;
                float2 v0; v0.x = acc[mf][nf][0]; v0.y = acc[mf][nf][1];
                float2 v1; v1.x = acc[mf][nf][2]; v1.y = acc[mf][nf][3];
                *(float2*)(C + (size_t)rr * N + col) = v0;
                *(float2*)(C + (size_t)(rr + 8) * N + col) = v1;
            }
        }
    }
}

// ---------------- bf16 hi/lo fragment packing with fused RoPE ------------------
__global__ __launch_bounds__(256) void pack_q(const float* __restrict__ QKV,
                                              uint4* __restrict__ Qpk)
{
    int idx = blockIdx.x * 256 + threadIdx.x;
    int lane = idx & 31, t = idx >> 5;
    int kc = t & 7; t >>= 3;
    int mt = t & 127; t >>= 7;
    int h = t & 31;
    int b = t >> 5;
    int g = lane >> 2, tg = lane & 3;
    const float scale = 0.08838834764831845f;
    const float ropeL = logf(10000.0f) / 64.0f;

    int c0 = kc * 16 + 2 * tg;
    int cp = c0 ^ 64;
    int s0 = mt * 16 + g;
    float sgn = (kc < 4) ? -1.f : 1.f;

    const float* base0 = QKV + (size_t)(b * SS + s0) * NQKV + h * HD;
    const float* base1 = base0 + (size_t)8 * NQKV;
    float2 a00 = *(const float2*)(base0 + c0);
    float2 a01 = *(const float2*)(base0 + c0 + 8);
    float2 p00 = *(const float2*)(base0 + cp);
    float2 p01 = *(const float2*)(base0 + cp + 8);
    float2 a10 = *(const float2*)(base1 + c0);
    float2 a11 = *(const float2*)(base1 + c0 + 8);
    float2 p10 = *(const float2*)(base1 + cp);
    float2 p11 = *(const float2*)(base1 + cp + 8);

    int jb = c0 & 63;
    float i0 = expf(-(float)jb * ropeL);
    float i1 = expf(-(float)(jb + 1) * ropeL);
    float i8 = expf(-(float)(jb + 8) * ropeL);
    float i9 = expf(-(float)(jb + 9) * ropeL);

    float sA = (float)s0, sB = (float)(s0 + 8);
    float v00x = (a00.x * cosf(sA * i0) + sgn * p00.x * sinf(sA * i0)) * scale;
    float v00y = (a00.y * cosf(sA * i1) + sgn * p00.y * sinf(sA * i1)) * scale;
    float v01x = (a01.x * cosf(sA * i8) + sgn * p01.x * sinf(sA * i8)) * scale;
    float v01y = (a01.y * cosf(sA * i9) + sgn * p01.y * sinf(sA * i9)) * scale;
    float v10x = (a10.x * cosf(sB * i0) + sgn * p10.x * sinf(sB * i0)) * scale;
    float v10y = (a10.y * cosf(sB * i1) + sgn * p10.y * sinf(sB * i1)) * scale;
    float v11x = (a11.x * cosf(sB * i8) + sgn * p11.x * sinf(sB * i8)) * scale;
    float v11y = (a11.y * cosf(sB * i9) + sgn * p11.y * sinf(sB * i9)) * scale;

    uint4 hi, lo;
    hi.x = bfpair(v00x, v00y); lo.x = bfpair_lo(v00x, v00y, hi.x);
    hi.y = bfpair(v10x, v10y); lo.y = bfpair_lo(v10x, v10y, hi.y);
    hi.z = bfpair(v01x, v01y); lo.z = bfpair_lo(v01x, v01y, hi.z);
    hi.w = bfpair(v11x, v11y); lo.w = bfpair_lo(v11x, v11y, hi.w);

    size_t o = ((((size_t)(b * 32 + h) * 128 + mt) * 8 + kc) * 64) + lane;
    Qpk[o] = hi;
    Qpk[o + 32] = lo;
}

__global__ __launch_bounds__(256) void pack_k(const float* __restrict__ QKV,
                                              uint4* __restrict__ Kpk)
{
    int idx = blockIdx.x * 256 + threadIdx.x;
    int lane = idx & 31, t = idx >> 5;
    int kc = t & 7; t >>= 3;
    int nt = t & 255; t >>= 8;
    int bkv = t;
    int b = bkv >> 3, kv = bkv & 7;
    int g = lane >> 2, tg = lane & 3;
    const float ropeL = logf(10000.0f) / 64.0f;

    int c0 = kc * 16 + 2 * tg;
    int cp = c0 ^ 64;
    int s0 = nt * 8 + g;
    float sgn = (kc < 4) ? -1.f : 1.f;

    const float* base = QKV + (size_t)(b * SS + s0) * NQKV + 4096 + kv * HD;
    float2 a0 = *(const float2*)(base + c0);
    float2 a1 = *(const float2*)(base + c0 + 8);
    float2 p0 = *(const float2*)(base + cp);
    float2 p1 = *(const float2*)(base + cp + 8);

    int jb = c0 & 63;
    float i0 = expf(-(float)jb * ropeL);
    float i1 = expf(-(float)(jb + 1) * ropeL);
    float i8 = expf(-(float)(jb + 8) * ropeL);
    float i9 = expf(-(float)(jb + 9) * ropeL);
    float s = (float)s0;

    float v0x = a0.x * cosf(s * i0) + sgn * p0.x * sinf(s * i0);
    float v0y = a0.y * cosf(s * i1) + sgn * p0.y * sinf(s * i1);
    float v1x = a1.x * cosf(s * i8) + sgn * p1.x * sinf(s * i8);
    float v1y = a1.y * cosf(s * i9) + sgn * p1.y * sinf(s * i9);

    uint4 o;
    o.x = bfpair(v0x, v0y);
    o.y = bfpair(v1x, v1y);
    o.z = bfpair_lo(v0x, v0y, o.x);
    o.w = bfpair_lo(v1x, v1y, o.y);
    Kpk[(((size_t)bkv * 256 + nt) * 8 + kc) * 32 + lane] = o;
}

__global__ __launch_bounds__(256) void pack_vt(const float* __restrict__ QKV,
                                               uint4* __restrict__ Vtp)
{
    int idx = blockIdx.x * 256 + threadIdx.x;
    int lane = idx & 31, t = idx >> 5;
    int kc = t & 3; t >>= 2;
    int nt = t & 15; t >>= 4;
    int vt = t & 31; t >>= 5;
    int bkv = t;
    int b = bkv >> 3, kv = bkv & 7;
    int g = lane >> 2, tg = lane & 3;

    int d = nt * 8 + g;
    int r0 = b * SS + vt * 64 + kc * 16 + 2 * tg;
    size_t col = 5120 + kv * HD + d;
    float x0 = QKV[(size_t)r0 * NQKV + col];
    float x1 = QKV[(size_t)(r0 + 1) * NQKV + col];
    float x2 = QKV[(size_t)(r0 + 8) * NQKV + col];
    float x3 = QKV[(size_t)(r0 + 9) * NQKV + col];
    uint4 o;
    o.x = bfpair(x0, x1);
    o.y = bfpair(x2, x3);
    o.z = bfpair_lo(x0, x1, o.x);
    o.w = bfpair_lo(x2, x3, o.y);
    Vtp[((((size_t)bkv * 32 + vt) * 16 + nt) * 4 + kc) * 32 + lane] = o;
}

// ---------------- Flash attention: fragment-direct, qt-balanced waves ----------
#define VPITCH 72

__device__ __forceinline__ void split_store(__nv_bfloat16* dh, __nv_bfloat16* dl,
                                            float x0, float x1) {
    __nv_bfloat16 h0 = __float2bfloat16(x0);
    __nv_bfloat16 h1 = __float2bfloat16(x1);
    __nv_bfloat162 hv; hv.x = h0; hv.y = h1;
    __nv_bfloat162 lv;
    lv.x = __float2bfloat16(x0 - __bfloat162float(h0));
    lv.y = __float2bfloat16(x1 - __bfloat162float(h1));
    *(__nv_bfloat162*)dh = hv;
    *(__nv_bfloat162*)dl = lv;
}

// grid = (NH, BB, SS/128): qt is the SLOWEST dim -> waves have uniform qt
__global__ __launch_bounds__(256, 1) void flash_mma(
    const uint4* __restrict__ Qpk, const uint4* __restrict__ Kpk,
    const uint4* __restrict__ Vtp, float* __restrict__ Aout)
{
    __shared__ __nv_bfloat16 Ph[128 * VPITCH];
    __shared__ __nv_bfloat16 Pl[128 * VPITCH];

    int tid = threadIdx.x, lane = tid & 31, wm = tid >> 5;
    int g = lane >> 2, tg = lane & 3;
    int h = blockIdx.x, b = blockIdx.y, qt = blockIdx.z;
    int bkv = b * NKV + (h >> 2);
    int q0 = qt * 128;
    const float NEGINF = __int_as_float(0xff800000);

    uint32_t qh[8][4], ql[8][4];
    {
        size_t qbase = (((size_t)(b * 32 + h) * 128 + qt * 8 + wm) * 8) * 64 + lane;
#pragma unroll
        for (int kc = 0; kc < 8; kc++) {
            uint4 hi = Qpk[qbase + (size_t)kc * 64];
            uint4 lo = Qpk[qbase + (size_t)kc * 64 + 32];
            qh[kc][0] = hi.x; qh[kc][1] = hi.y; qh[kc][2] = hi.z; qh[kc][3] = hi.w;
            ql[kc][0] = lo.x; ql[kc][1] = lo.y; ql[kc][2] = lo.z; ql[kc][3] = lo.w;
        }
    }

    float accO[16][4];
#pragma unroll
    for (int nf = 0; nf < 16; nf++)
#pragma unroll
        for (int i = 0; i < 4; i++) accO[nf][i] = 0.f;
    float m0 = NEGINF, m1 = NEGINF, l0 = 0.f, l1 = 0.f;

    const uint4* kBase = Kpk + ((size_t)bkv * 256) * 8 * 32 + lane;
    const uint4* vBase = Vtp + ((size_t)bkv * 32) * 16 * 4 * 32 + lane;

    int nkt = (q0 + wm * 16 + 15) / 64 + 1;
    for (int kt = 0; kt < nkt; kt++) {
        int k0g = kt * 64;
        float S[8][4];
#pragma unroll
        for (int nf = 0; nf < 8; nf++)
#pragma unroll
            for (int i = 0; i < 4; i++) S[nf][i] = 0.f;

#pragma unroll
        for (int kc = 0; kc < 8; kc++) {
#pragma unroll
            for (int nf = 0; nf < 8; nf++) {
                uint4 kk = kBase[(((size_t)(kt * 8 + nf)) * 8 + kc) * 32];
                mma_bf16(S[nf], qh[kc], kk.x, kk.y);
                mma_bf16(S[nf], qh[kc], kk.z, kk.w);
                mma_bf16(S[nf], ql[kc], kk.x, kk.y);
            }
        }
        if (k0g + 63 > q0 + wm * 16) {
            int row0 = q0 + wm * 16 + g, row1 = row0 + 8;
#pragma unroll
            for (int nf = 0; nf < 8; nf++) {
                int col = k0g + nf * 8 + 2 * tg;
                if (col     > row0) S[nf][0] = NEGINF;
                if (col + 1 > row0) S[nf][1] = NEGINF;
                if (col     > row1) S[nf][2] = NEGINF;
                if (col + 1 > row1) S[nf][3] = NEGINF;
            }
        }
        float mx0 = NEGINF, mx1 = NEGINF;
#pragma unroll
        for (int nf = 0; nf < 8; nf++) {
            mx0 = fmaxf(mx0, fmaxf(S[nf][0], S[nf][1]));
            mx1 = fmaxf(mx1, fmaxf(S[nf][2], S[nf][3]));
        }
        mx0 = fmaxf(mx0, __shfl_xor_sync(0xffffffff, mx0, 1));
        mx0 = fmaxf(mx0, __shfl_xor_sync(0xffffffff, mx0, 2));
        mx1 = fmaxf(mx1, __shfl_xor_sync(0xffffffff, mx1, 1));
        mx1 = fmaxf(mx1, __shfl_xor_sync(0xffffffff, mx1, 2));
        float m0n = fmaxf(m0, mx0), m1n = fmaxf(m1, mx1);
        float al0 = __expf(m0 - m0n), al1 = __expf(m1 - m1n);
        m0 = m0n; m1 = m1n;

        __syncwarp();
        float sum0 = 0.f, sum1 = 0.f;
        int pr0 = (wm * 16 + g) * VPITCH, pr1 = (wm * 16 + g + 8) * VPITCH;
#pragma unroll
        for (int nf = 0; nf < 8; nf++) {
            float p00 = __expf(S[nf][0] - m0);
            float p01 = __expf(S[nf][1] - m0);
            float p10 = __expf(S[nf][2] - m1);
            float p11 = __expf(S[nf][3] - m1);
            sum0 += p00 + p01;
            sum1 += p10 + p11;
            int co = nf * 8 + 2 * tg;
            split_store(Ph + pr0 + co, Pl + pr0 + co, p00, p01);
            split_store(Ph + pr1 + co, Pl + pr1 + co, p10, p11);
        }
        sum0 += __shfl_xor_sync(0xffffffff, sum0, 1);
        sum0 += __shfl_xor_sync(0xffffffff, sum0, 2);
        sum1 += __shfl_xor_sync(0xffffffff, sum1, 1);
        sum1 += __shfl_xor_sync(0xffffffff, sum1, 2);
        l0 = l0 * al0 + sum0;
        l1 = l1 * al1 + sum1;
#pragma unroll
        for (int nf = 0; nf < 16; nf++) {
            accO[nf][0] *= al0; accO[nf][1] *= al0;
            accO[nf][2] *= al1; accO[nf][3] *= al1;
        }
        __syncwarp();
#pragma unroll
        for (int kc = 0; kc < 4; kc++) {
            uint32_t pah[4], pal[4];
            const __nv_bfloat16* pb = Ph + (wm * 16 + g) * VPITCH + kc * 16 + 2 * tg;
            pah[0] = *(const uint32_t*)(pb);
            pah[1] = *(const uint32_t*)(pb + 8 * VPITCH);
            pah[2] = *(const uint32_t*)(pb + 8);
            pah[3] = *(const uint32_t*)(pb + 8 * VPITCH + 8);
            const __nv_bfloat16* pl = Pl + (wm * 16 + g) * VPITCH + kc * 16 + 2 * tg;
            pal[0] = *(const uint32_t*)(pl);
            pal[1] = *(const uint32_t*)(pl + 8 * VPITCH);
            pal[2] = *(const uint32_t*)(pl + 8);
            pal[3] = *(const uint32_t*)(pl + 8 * VPITCH + 8);
#pragma unroll
            for (int nf = 0; nf < 16; nf++) {
                uint4 vv = vBase[((((size_t)kt * 16 + nf) * 4) + kc) * 32];
                mma_bf16(accO[nf], pah, vv.x, vv.y);
                mma_bf16(accO[nf], pah, vv.z, vv.w);
                mma_bf16(accO[nf], pal, vv.x, vv.y);
            }
        }
    }

    float i0 = 1.0f / l0, i1 = 1.0f / l1;
    int r0 = q0 + wm * 16 + g;
    float* o0 = Aout + (((size_t)b * SS + r0) * NH + h) * HD;
    float* o1 = o0 + (size_t)8 * NH * HD;
#pragma unroll
    for (int nf = 0; nf < 16; nf++) {
        int d = nf * 8 + 2 * tg;
        float2 v0; v0.x = accO[nf][0] * i0; v0.y = accO[nf][1] * i0;
        float2 v1; v1.x = accO[nf][2] * i1; v1.y = accO[nf][3] * i1;
        *(float2*)(o0 + d) = v0;
        *(float2*)(o1 + d) = v1;
    }
}

// ---------------- launch --------------------------------------------------------
extern "C" void kernel_launch(void* const* d_in, const int* in_sizes, int n_in,
                              void* d_out, int out_size)
{
    const float* x  = (const float*)d_in[0];
    const float* wq = (const float*)d_in[1];
    const float* wk = (const float*)d_in[2];
    const float* wv = (const float*)d_in[3];
    const float* wo = (const float*)d_in[4];
    float* out = (float*)d_out;

    float *QKV, *Ap;
    uint32_t *Xp, *Apk, *Wqkvp, *Wop;
    uint4 *Qpk, *Kpk, *Vtp;
    cudaGetSymbolAddress((void**)&QKV, g_QKV);
    cudaGetSymbolAddress((void**)&Ap, g_A);
    cudaGetSymbolAddress((void**)&Xp, g_Xp);
    cudaGetSymbolAddress((void**)&Apk, g_Apk);
    cudaGetSymbolAddress((void**)&Wqkvp, g_Wqkvp);
    cudaGetSymbolAddress((void**)&Wop, g_Wop);
    cudaGetSymbolAddress((void**)&Qpk, g_Qpk);
    cudaGetSymbolAddress((void**)&Kpk, g_Kpk);
    cudaGetSymbolAddress((void**)&Vtp, g_Vtp);

    int smcount = 148;
    cudaDeviceGetAttribute(&smcount, cudaDevAttrMultiProcessorCount, 0);
    int pgrid = 2 * smcount;

    const int KT = HIDDEN / 8;   // 512

    // pack GEMM operands
    pack_a<<<(MROWS/16)*(HIDDEN/8)*32/256, 256>>>(x, Xp, MROWS, HIDDEN);
    pack_b<<<((NH*HD)/8)*KT*32/256, 256>>>(wq, Wqkvp, NH*HD, HIDDEN);
    pack_b<<<((NKV*HD)/8)*KT*32/256, 256>>>(wk, Wqkvp + (size_t)512*KT*32*2, NKV*HD, HIDDEN);
    pack_b<<<((NKV*HD)/8)*KT*32/256, 256>>>(wv, Wqkvp + (size_t)640*KT*32*2, NKV*HD, HIDDEN);

    // fused QKV projection (persistent, banded walk)
    gemm_fp<<<pgrid, 256>>>(Xp, Wqkvp, QKV, MROWS, NQKV, HIDDEN);

    // bf16 hi/lo fragment packs (RoPE fused)
    pack_q<<<BB*NH*128*8*32/256, 256>>>(QKV, Qpk);
    pack_k<<<BB*NKV*256*8*32/256, 256>>>(QKV, Kpk);
    pack_vt<<<BB*NKV*32*16*4*32/256, 256>>>(QKV, Vtp);

    // flash attention — qt slowest grid dim for balanced waves
    flash_mma<<<dim3(NH, BB, SS/128), 256>>>(Qpk, Kpk, Vtp, Ap);

    // output projection
    pack_b<<<(HIDDEN/8)*((NH*HD)/8)*32/256, 256>>>(wo, Wop, HIDDEN, NH*HD);
    pack_a<<<(MROWS/16)*((NH*HD)/8)*32/256, 256>>>(Ap, Apk, MROWS, NH*HD);
    gemm_fp<<<pgrid, 256>>>(Apk, Wop, out, MROWS, HIDDEN, NH*HD);
}

// round 15
// speedup vs baseline: 1.0760x; 1.0144x over previous
#include <cuda_runtime.h>
#include <cuda_bf16.h>
#include <math.h>
#include <stdint.h>

#define HIDDEN 4096
#define NH 32
#define NKV 8
#define HD 128
#define BB 2
#define SS 2048
#define MROWS (BB*SS)   /* 4096 */
#define NQKV 6144       /* 4096 + 1024 + 1024 */

// ---------------- scratch -----------------------------------------------------
__device__ float g_QKV[(size_t)MROWS * NQKV];
__device__ uint32_t g_Xp   [(size_t)MROWS * HIDDEN];
__device__ uint32_t g_Apk  [(size_t)MROWS * NH * HD];   // attn out, tf32 A-frags
__device__ uint32_t g_Wqkvp[(size_t)NQKV * HIDDEN];
__device__ uint32_t g_Wop  [(size_t)HIDDEN * NH * HD];
__device__ uint4 g_Qpk[(size_t)BB * NH * 128 * 8 * 64];
__device__ uint4 g_Kpk[(size_t)BB * NKV * 256 * 8 * 32];
__device__ uint4 g_Vtp[(size_t)BB * NKV * 32 * 16 * 4 * 32];

__device__ __forceinline__ uint32_t f2tf32(float f) {
    uint32_t r; asm("cvt.rna.tf32.f32 %0, %1;" : "=r"(r) : "f"(f)); return r;
}
__device__ __forceinline__ uint32_t bfpair(float x0, float x1) {
    __nv_bfloat162 h; h.x = __float2bfloat16(x0); h.y = __float2bfloat16(x1);
    return *(uint32_t*)&h;
}
__device__ __forceinline__ uint32_t bfpair_lo(float x0, float x1, uint32_t hi) {
    __nv_bfloat162 h = *(__nv_bfloat162*)&hi;
    return bfpair(x0 - __bfloat162float(h.x), x1 - __bfloat162float(h.y));
}

__device__ __forceinline__ void mma16n8k8(float* d, const uint32_t* a,
                                          uint32_t b0, uint32_t b1) {
    asm volatile(
        "mma.sync.aligned.m16n8k8.row.col.f32.tf32.tf32.f32 "
        "{%0,%1,%2,%3}, {%4,%5,%6,%7}, {%8,%9}, {%0,%1,%2,%3};"
        : "+f"(d[0]), "+f"(d[1]), "+f"(d[2]), "+f"(d[3])
        : "r"(a[0]), "r"(a[1]), "r"(a[2]), "r"(a[3]), "r"(b0), "r"(b1));
}
__device__ __forceinline__ void mma_bf16(float* d, const uint32_t* a,
                                         uint32_t b0, uint32_t b1) {
    asm volatile(
        "mma.sync.aligned.m16n8k16.row.col.f32.bf16.bf16.f32 "
        "{%0,%1,%2,%3}, {%4,%5,%6,%7}, {%8,%9}, {%0,%1,%2,%3};"
        : "+f"(d[0]), "+f"(d[1]), "+f"(d[2]), "+f"(d[3])
        : "r"(a[0]), "r"(a[1]), "r"(a[2]), "r"(a[3]), "r"(b0), "r"(b1));
}

// ---------------- tf32 packing (GEMM operands) ---------------------------------
__global__ __launch_bounds__(256) void pack_a(const float* __restrict__ X,
                                              uint32_t* __restrict__ Xp,
                                              int M, int K)
{
    int idx = blockIdx.x * 256 + threadIdx.x;
    int total = (M >> 4) * (K >> 3) * 32;
    if (idx >= total) return;
    int lane = idx & 31, t = idx >> 5;
    int KT = K >> 3;
    int kt = t % KT, mt = t / KT;
    int g = lane >> 2, tg = lane & 3;
    size_t r0 = (size_t)(mt * 16 + g) * K + kt * 8 + tg;
    uint4 v;
    v.x = f2tf32(X[r0]);
    v.y = f2tf32(X[r0 + (size_t)8 * K]);
    v.z = f2tf32(X[r0 + 4]);
    v.w = f2tf32(X[r0 + (size_t)8 * K + 4]);
    ((uint4*)Xp)[(size_t)t * 32 + lane] = v;
}

__global__ __launch_bounds__(256) void pack_b(const float* __restrict__ W,
                                              uint32_t* __restrict__ Wp,
                                              int N, int K)
{
    int idx = blockIdx.x * 256 + threadIdx.x;
    int total = (N >> 3) * (K >> 3) * 32;
    if (idx >= total) return;
    int lane = idx & 31, t = idx >> 5;
    int KT = K >> 3;
    int kt = t % KT, nt = t / KT;
    int g = lane >> 2, tg = lane & 3;
    size_t r0 = (size_t)(nt * 8 + g) * K + kt * 8 + tg;
    uint2 v;
    v.x = f2tf32(W[r0]);
    v.y = f2tf32(W[r0 + 4]);
    ((uint2*)Wp)[(size_t)t * 32 + lane] = v;
}

// ---------------- persistent fragment-direct TF32 GEMM: C = A * W^T ------------
__global__ __launch_bounds__(256, 2) void gemm_fp(
    const uint32_t* __restrict__ Apk, const uint32_t* __restrict__ Bp,
    float* __restrict__ C, int M, int N, int K)
{
    int tid = threadIdx.x;
    int lane = tid & 31, wid = tid >> 5;
    int wm = wid & 1, wn = wid >> 1;
    int g = lane >> 2, tg = lane & 3;
    const int KT = K >> 3;
    const int ntn = N >> 7;
    const int ntm = M >> 7;
    const int ntiles = ntm * ntn;
    const int BAND = 8;
    const int perBand = ntm * BAND;
    const size_t aStep = (size_t)KT * 32;
    const size_t bStep = (size_t)KT * 32;

    for (int tIdx = blockIdx.x; tIdx < ntiles; tIdx += gridDim.x) {
        int bi = tIdx / perBand;
        int r  = tIdx % perBand;
        int m0 = (r / BAND) << 7;
        int n0 = (bi * BAND + (r % BAND)) << 7;

        const uint4* aP = (const uint4*)Apk + ((size_t)((m0 >> 4) + wm * 4) * KT) * 32 + lane;
        const uint2* bP = (const uint2*)Bp + ((size_t)((n0 >> 3) + wn * 4) * KT) * 32 + lane;

        float acc[4][4][4];
#pragma unroll
        for (int mf = 0; mf < 4; mf++)
#pragma unroll
            for (int nf = 0; nf < 4; nf++)
#pragma unroll
                for (int i = 0; i < 4; i++) acc[mf][nf][i] = 0.f;

#define LOADA(dst, kt) do { \
        _Pragma("unroll") \
        for (int mf = 0; mf < 4; mf++) { \
            uint4 u = aP[(size_t)mf * aStep + (size_t)(kt) * 32]; \
            dst[mf][0] = u.x; dst[mf][1] = u.y; dst[mf][2] = u.z; dst[mf][3] = u.w; \
        } \
    } while (0)
#define LOADB(dst, kt) do { \
        _Pragma("unroll") \
        for (int nf = 0; nf < 4; nf++) { \
            uint2 u = bP[(size_t)nf * bStep + (size_t)(kt) * 32]; \
            dst[nf][0] = u.x; dst[nf][1] = u.y; \
        } \
    } while (0)
#define DOMMA(a, b) do { \
        _Pragma("unroll") \
        for (int nf = 0; nf < 4; nf++) \
            _Pragma("unroll") \
            for (int mf = 0; mf < 4; mf++) \
                mma16n8k8(acc[mf][nf], a[mf], b[nf][0], b[nf][1]); \
    } while (0)

        uint32_t aA[4][4], aB[4][4], bA[4][2], bB[4][2];
        LOADA(aA, 0); LOADB(bA, 0);
        for (int kt = 0; kt < KT; kt += 2) {
            LOADA(aB, kt + 1); LOADB(bB, kt + 1);
            DOMMA(aA, bA);
            if (kt + 2 < KT) { LOADA(aA, kt + 2); LOADB(bA, kt + 2); }
            DOMMA(aB, bB);
        }
#undef LOADA
#undef LOADB
#undef DOMMA

#pragma unroll
        for (int mf = 0; mf < 4; mf++) {
            int rr = m0 + wm * 64 + mf * 16 + g;
#pragma unroll
            for (int nf = 0; nf < 4; nf++) {
                int col = n0 + wn * 32 + nf * 8 + 2 * tg;
                float2 v0; v0.x = acc[mf][nf][0]; v0.y = acc[mf][nf][1];
                float2 v1; v1.x = acc[mf][nf][2]; v1.y = acc[mf][nf][3];
                *(float2*)(C + (size_t)rr * N + col) = v0;
                *(float2*)(C + (size_t)(rr + 8) * N + col) = v1;
            }
        }
    }
}

// ---------------- bf16 hi/lo fragment packing with fused RoPE ------------------
__global__ __launch_bounds__(256) void pack_q(const float* __restrict__ QKV,
                                              uint4* __restrict__ Qpk)
{
    int idx = blockIdx.x * 256 + threadIdx.x;
    int lane = idx & 31, t = idx >> 5;
    int kc = t & 7; t >>= 3;
    int mt = t & 127; t >>= 7;
    int h = t & 31;
    int b = t >> 5;
    int g = lane >> 2, tg = lane & 3;
    const float scale = 0.08838834764831845f;
    const float ropeL = logf(10000.0f) / 64.0f;

    int c0 = kc * 16 + 2 * tg;
    int cp = c0 ^ 64;
    int s0 = mt * 16 + g;
    float sgn = (kc < 4) ? -1.f : 1.f;

    const float* base0 = QKV + (size_t)(b * SS + s0) * NQKV + h * HD;
    const float* base1 = base0 + (size_t)8 * NQKV;
    float2 a00 = *(const float2*)(base0 + c0);
    float2 a01 = *(const float2*)(base0 + c0 + 8);
    float2 p00 = *(const float2*)(base0 + cp);
    float2 p01 = *(const float2*)(base0 + cp + 8);
    float2 a10 = *(const float2*)(base1 + c0);
    float2 a11 = *(const float2*)(base1 + c0 + 8);
    float2 p10 = *(const float2*)(base1 + cp);
    float2 p11 = *(const float2*)(base1 + cp + 8);

    int jb = c0 & 63;
    float i0 = expf(-(float)jb * ropeL);
    float i1 = expf(-(float)(jb + 1) * ropeL);
    float i8 = expf(-(float)(jb + 8) * ropeL);
    float i9 = expf(-(float)(jb + 9) * ropeL);

    float sA = (float)s0, sB = (float)(s0 + 8);
    float v00x = (a00.x * cosf(sA * i0) + sgn * p00.x * sinf(sA * i0)) * scale;
    float v00y = (a00.y * cosf(sA * i1) + sgn * p00.y * sinf(sA * i1)) * scale;
    float v01x = (a01.x * cosf(sA * i8) + sgn * p01.x * sinf(sA * i8)) * scale;
    float v01y = (a01.y * cosf(sA * i9) + sgn * p01.y * sinf(sA * i9)) * scale;
    float v10x = (a10.x * cosf(sB * i0) + sgn * p10.x * sinf(sB * i0)) * scale;
    float v10y = (a10.y * cosf(sB * i1) + sgn * p10.y * sinf(sB * i1)) * scale;
    float v11x = (a11.x * cosf(sB * i8) + sgn * p11.x * sinf(sB * i8)) * scale;
    float v11y = (a11.y * cosf(sB * i9) + sgn * p11.y * sinf(sB * i9)) * scale;

    uint4 hi, lo;
    hi.x = bfpair(v00x, v00y); lo.x = bfpair_lo(v00x, v00y, hi.x);
    hi.y = bfpair(v10x, v10y); lo.y = bfpair_lo(v10x, v10y, hi.y);
    hi.z = bfpair(v01x, v01y); lo.z = bfpair_lo(v01x, v01y, hi.z);
    hi.w = bfpair(v11x, v11y); lo.w = bfpair_lo(v11x, v11y, hi.w);

    size_t o = ((((size_t)(b * 32 + h) * 128 + mt) * 8 + kc) * 64) + lane;
    Qpk[o] = hi;
    Qpk[o + 32] = lo;
}

__global__ __launch_bounds__(256) void pack_k(const float* __restrict__ QKV,
                                              uint4* __restrict__ Kpk)
{
    int idx = blockIdx.x * 256 + threadIdx.x;
    int lane = idx & 31, t = idx >> 5;
    int kc = t & 7; t >>= 3;
    int nt = t & 255; t >>= 8;
    int bkv = t;
    int b = bkv >> 3, kv = bkv & 7;
    int g = lane >> 2, tg = lane & 3;
    const float ropeL = logf(10000.0f) / 64.0f;

    int c0 = kc * 16 + 2 * tg;
    int cp = c0 ^ 64;
    int s0 = nt * 8 + g;
    float sgn = (kc < 4) ? -1.f : 1.f;

    const float* base = QKV + (size_t)(b * SS + s0) * NQKV + 4096 + kv * HD;
    float2 a0 = *(const float2*)(base + c0);
    float2 a1 = *(const float2*)(base + c0 + 8);
    float2 p0 = *(const float2*)(base + cp);
    float2 p1 = *(const float2*)(base + cp + 8);

    int jb = c0 & 63;
    float i0 = expf(-(float)jb * ropeL);
    float i1 = expf(-(float)(jb + 1) * ropeL);
    float i8 = expf(-(float)(jb + 8) * ropeL);
    float i9 = expf(-(float)(jb + 9) * ropeL);
    float s = (float)s0;

    float v0x = a0.x * cosf(s * i0) + sgn * p0.x * sinf(s * i0);
    float v0y = a0.y * cosf(s * i1) + sgn * p0.y * sinf(s * i1);
    float v1x = a1.x * cosf(s * i8) + sgn * p1.x * sinf(s * i8);
    float v1y = a1.y * cosf(s * i9) + sgn * p1.y * sinf(s * i9);

    uint4 o;
    o.x = bfpair(v0x, v0y);
    o.y = bfpair(v1x, v1y);
    o.z = bfpair_lo(v0x, v0y, o.x);
    o.w = bfpair_lo(v1x, v1y, o.y);
    Kpk[(((size_t)bkv * 256 + nt) * 8 + kc) * 32 + lane] = o;
}

__global__ __launch_bounds__(256) void pack_vt(const float* __restrict__ QKV,
                                               uint4* __restrict__ Vtp)
{
    int idx = blockIdx.x * 256 + threadIdx.x;
    int lane = idx & 31, t = idx >> 5;
    int kc = t & 3; t >>= 2;
    int nt = t & 15; t >>= 4;
    int vt = t & 31; t >>= 5;
    int bkv = t;
    int b = bkv >> 3, kv = bkv & 7;
    int g = lane >> 2, tg = lane & 3;

    int d = nt * 8 + g;
    int r0 = b * SS + vt * 64 + kc * 16 + 2 * tg;
    size_t col = 5120 + kv * HD + d;
    float x0 = QKV[(size_t)r0 * NQKV + col];
    float x1 = QKV[(size_t)(r0 + 1) * NQKV + col];
    float x2 = QKV[(size_t)(r0 + 8) * NQKV + col];
    float x3 = QKV[(size_t)(r0 + 9) * NQKV + col];
    uint4 o;
    o.x = bfpair(x0, x1);
    o.y = bfpair(x2, x3);
    o.z = bfpair_lo(x0, x1, o.x);
    o.w = bfpair_lo(x2, x3, o.y);
    Vtp[((((size_t)bkv * 32 + vt) * 16 + nt) * 4 + kc) * 32 + lane] = o;
}

// ---------------- Flash attention: fragment-direct, packed-A epilogue ----------
#define VPITCH 72

__device__ __forceinline__ void split_store(__nv_bfloat16* dh, __nv_bfloat16* dl,
                                            float x0, float x1) {
    __nv_bfloat16 h0 = __float2bfloat16(x0);
    __nv_bfloat16 h1 = __float2bfloat16(x1);
    __nv_bfloat162 hv; hv.x = h0; hv.y = h1;
    __nv_bfloat162 lv;
    lv.x = __float2bfloat16(x0 - __bfloat162float(h0));
    lv.y = __float2bfloat16(x1 - __bfloat162float(h1));
    *(__nv_bfloat162*)dh = hv;
    *(__nv_bfloat162*)dl = lv;
}

// grid = (NH, BB, SS/128): qt slowest -> balanced waves.
// Epilogue writes tf32 A-fragments for the wo GEMM directly (shuffle remap).
__global__ __launch_bounds__(256, 1) void flash_mma(
    const uint4* __restrict__ Qpk, const uint4* __restrict__ Kpk,
    const uint4* __restrict__ Vtp, uint32_t* __restrict__ Apk)
{
    __shared__ __nv_bfloat16 Ph[128 * VPITCH];
    __shared__ __nv_bfloat16 Pl[128 * VPITCH];

    int tid = threadIdx.x, lane = tid & 31, wm = tid >> 5;
    int g = lane >> 2, tg = lane & 3;
    int h = blockIdx.x, b = blockIdx.y, qt = blockIdx.z;
    int bkv = b * NKV + (h >> 2);
    int q0 = qt * 128;
    const float NEGINF = __int_as_float(0xff800000);

    uint32_t qh[8][4], ql[8][4];
    {
        size_t qbase = (((size_t)(b * 32 + h) * 128 + qt * 8 + wm) * 8) * 64 + lane;
#pragma unroll
        for (int kc = 0; kc < 8; kc++) {
            uint4 hi = Qpk[qbase + (size_t)kc * 64];
            uint4 lo = Qpk[qbase + (size_t)kc * 64 + 32];
            qh[kc][0] = hi.x; qh[kc][1] = hi.y; qh[kc][2] = hi.z; qh[kc][3] = hi.w;
            ql[kc][0] = lo.x; ql[kc][1] = lo.y; ql[kc][2] = lo.z; ql[kc][3] = lo.w;
        }
    }

    float accO[16][4];
#pragma unroll
    for (int nf = 0; nf < 16; nf++)
#pragma unroll
        for (int i = 0; i < 4; i++) accO[nf][i] = 0.f;
    float m0 = NEGINF, m1 = NEGINF, l0 = 0.f, l1 = 0.f;

    const uint4* kBase = Kpk + ((size_t)bkv * 256) * 8 * 32 + lane;
    const uint4* vBase = Vtp + ((size_t)bkv * 32) * 16 * 4 * 32 + lane;

    int nkt = (q0 + wm * 16 + 15) / 64 + 1;
    for (int kt = 0; kt < nkt; kt++) {
        int k0g = kt * 64;
        float S[8][4];
#pragma unroll
        for (int nf = 0; nf < 8; nf++)
#pragma unroll
            for (int i = 0; i < 4; i++) S[nf][i] = 0.f;

#pragma unroll
        for (int kc = 0; kc < 8; kc++) {
#pragma unroll
            for (int nf = 0; nf < 8; nf++) {
                uint4 kk = kBase[(((size_t)(kt * 8 + nf)) * 8 + kc) * 32];
                mma_bf16(S[nf], qh[kc], kk.x, kk.y);
                mma_bf16(S[nf], qh[kc], kk.z, kk.w);
                mma_bf16(S[nf], ql[kc], kk.x, kk.y);
            }
        }
        if (k0g + 63 > q0 + wm * 16) {
            int row0 = q0 + wm * 16 + g, row1 = row0 + 8;
#pragma unroll
            for (int nf = 0; nf < 8; nf++) {
                int col = k0g + nf * 8 + 2 * tg;
                if (col     > row0) S[nf][0] = NEGINF;
                if (col + 1 > row0) S[nf][1] = NEGINF;
                if (col     > row1) S[nf][2] = NEGINF;
                if (col + 1 > row1) S[nf][3] = NEGINF;
            }
        }
        float mx0 = NEGINF, mx1 = NEGINF;
#pragma unroll
        for (int nf = 0; nf < 8; nf++) {
            mx0 = fmaxf(mx0, fmaxf(S[nf][0], S[nf][1]));
            mx1 = fmaxf(mx1, fmaxf(S[nf][2], S[nf][3]));
        }
        mx0 = fmaxf(mx0, __shfl_xor_sync(0xffffffff, mx0, 1));
        mx0 = fmaxf(mx0, __shfl_xor_sync(0xffffffff, mx0, 2));
        mx1 = fmaxf(mx1, __shfl_xor_sync(0xffffffff, mx1, 1));
        mx1 = fmaxf(mx1, __shfl_xor_sync(0xffffffff, mx1, 2));
        float m0n = fmaxf(m0, mx0), m1n = fmaxf(m1, mx1);
        float al0 = __expf(m0 - m0n), al1 = __expf(m1 - m1n);
        m0 = m0n; m1 = m1n;

        __syncwarp();
        float sum0 = 0.f, sum1 = 0.f;
        int pr0 = (wm * 16 + g) * VPITCH, pr1 = (wm * 16 + g + 8) * VPITCH;
#pragma unroll
        for (int nf = 0; nf < 8; nf++) {
            float p00 = __expf(S[nf][0] - m0);
            float p01 = __expf(S[nf][1] - m0);
            float p10 = __expf(S[nf][2] - m1);
            float p11 = __expf(S[nf][3] - m1);
            sum0 += p00 + p01;
            sum1 += p10 + p11;
            int co = nf * 8 + 2 * tg;
            split_store(Ph + pr0 + co, Pl + pr0 + co, p00, p01);
            split_store(Ph + pr1 + co, Pl + pr1 + co, p10, p11);
        }
        sum0 += __shfl_xor_sync(0xffffffff, sum0, 1);
        sum0 += __shfl_xor_sync(0xffffffff, sum0, 2);
        sum1 += __shfl_xor_sync(0xffffffff, sum1, 1);
        sum1 += __shfl_xor_sync(0xffffffff, sum1, 2);
        l0 = l0 * al0 + sum0;
        l1 = l1 * al1 + sum1;
#pragma unroll
        for (int nf = 0; nf < 16; nf++) {
            accO[nf][0] *= al0; accO[nf][1] *= al0;
            accO[nf][2] *= al1; accO[nf][3] *= al1;
        }
        __syncwarp();
#pragma unroll
        for (int kc = 0; kc < 4; kc++) {
            uint32_t pah[4], pal[4];
            const __nv_bfloat16* pb = Ph + (wm * 16 + g) * VPITCH + kc * 16 + 2 * tg;
            pah[0] = *(const uint32_t*)(pb);
            pah[1] = *(const uint32_t*)(pb + 8 * VPITCH);
            pah[2] = *(const uint32_t*)(pb + 8);
            pah[3] = *(const uint32_t*)(pb + 8 * VPITCH + 8);
            const __nv_bfloat16* pl = Pl + (wm * 16 + g) * VPITCH + kc * 16 + 2 * tg;
            pal[0] = *(const uint32_t*)(pl);
            pal[1] = *(const uint32_t*)(pl + 8 * VPITCH);
            pal[2] = *(const uint32_t*)(pl + 8);
            pal[3] = *(const uint32_t*)(pl + 8 * VPITCH + 8);
#pragma unroll
            for (int nf = 0; nf < 16; nf++) {
                uint4 vv = vBase[((((size_t)kt * 16 + nf) * 4) + kc) * 32];
                mma_bf16(accO[nf], pah, vv.x, vv.y);
                mma_bf16(accO[nf], pah, vv.z, vv.w);
                mma_bf16(accO[nf], pal, vv.x, vv.y);
            }
        }
    }

    // ---- epilogue: write tf32 A-fragments for wo GEMM directly ----
    // A-frag (m16k8): lane(g,tg) = {A[m+g, k+tg], A[m+g+8, k+tg],
    //                               A[m+g, k+tg+4], A[m+g+8, k+tg+4]}
    // accO lane(g,tg) owns cols (2tg, 2tg+1): remap via 4-lane shuffles.
    float i0 = 1.0f / l0, i1 = 1.0f / l1;
    int mt = (b * SS + q0 + wm * 16) >> 4;
    int baseL = lane & ~3;
    int s1 = baseL + (tg >> 1);
    int s2 = s1 + 2;
    bool odd = (tg & 1) != 0;
    const int KTO = (NH * HD) >> 3;   // 512
#pragma unroll
    for (int nf = 0; nf < 16; nf++) {
        float a0 = accO[nf][0] * i0;
        float a1 = accO[nf][1] * i0;
        float c0 = accO[nf][2] * i1;
        float c1 = accO[nf][3] * i1;
        float r0a = __shfl_sync(0xffffffffu, a0, s1);
        float r0b = __shfl_sync(0xffffffffu, a1, s1);
        float r8a = __shfl_sync(0xffffffffu, c0, s1);
        float r8b = __shfl_sync(0xffffffffu, c1, s1);
        float t0a = __shfl_sync(0xffffffffu, a0, s2);
        float t0b = __shfl_sync(0xffffffffu, a1, s2);
        float t8a = __shfl_sync(0xffffffffu, c0, s2);
        float t8b = __shfl_sync(0xffffffffu, c1, s2);
        uint4 v;
        v.x = f2tf32(odd ? r0b : r0a);
        v.y = f2tf32(odd ? r8b : r8a);
        v.z = f2tf32(odd ? t0b : t0a);
        v.w = f2tf32(odd ? t8b : t8a);
        int kc = h * 16 + nf;
        ((uint4*)Apk)[((size_t)mt * KTO + kc) * 32 + lane] = v;
    }
}

// ---------------- launch --------------------------------------------------------
extern "C" void kernel_launch(void* const* d_in, const int* in_sizes, int n_in,
                              void* d_out, int out_size)
{
    const float* x  = (const float*)d_in[0];
    const float* wq = (const float*)d_in[1];
    const float* wk = (const float*)d_in[2];
    const float* wv = (const float*)d_in[3];
    const float* wo = (const float*)d_in[4];
    float* out = (float*)d_out;

    float *QKV;
    uint32_t *Xp, *Apk, *Wqkvp, *Wop;
    uint4 *Qpk, *Kpk, *Vtp;
    cudaGetSymbolAddress((void**)&QKV, g_QKV);
    cudaGetSymbolAddress((void**)&Xp, g_Xp);
    cudaGetSymbolAddress((void**)&Apk, g_Apk);
    cudaGetSymbolAddress((void**)&Wqkvp, g_Wqkvp);
    cudaGetSymbolAddress((void**)&Wop, g_Wop);
    cudaGetSymbolAddress((void**)&Qpk, g_Qpk);
    cudaGetSymbolAddress((void**)&Kpk, g_Kpk);
    cudaGetSymbolAddress((void**)&Vtp, g_Vtp);

    int smcount = 148;
    cudaDeviceGetAttribute(&smcount, cudaDevAttrMultiProcessorCount, 0);
    int pgrid = 2 * smcount;

    const int KT = HIDDEN / 8;   // 512

    // pack GEMM operands
    pack_a<<<(MROWS/16)*(HIDDEN/8)*32/256, 256>>>(x, Xp, MROWS, HIDDEN);
    pack_b<<<((NH*HD)/8)*KT*32/256, 256>>>(wq, Wqkvp, NH*HD, HIDDEN);
    pack_b<<<((NKV*HD)/8)*KT*32/256, 256>>>(wk, Wqkvp + (size_t)512*KT*32*2, NKV*HD, HIDDEN);
    pack_b<<<((NKV*HD)/8)*KT*32/256, 256>>>(wv, Wqkvp + (size_t)640*KT*32*2, NKV*HD, HIDDEN);

    // fused QKV projection (persistent, banded walk)
    gemm_fp<<<pgrid, 256>>>(Xp, Wqkvp, QKV, MROWS, NQKV, HIDDEN);

    // bf16 hi/lo fragment packs (RoPE fused)
    pack_q<<<BB*NH*128*8*32/256, 256>>>(QKV, Qpk);
    pack_k<<<BB*NKV*256*8*32/256, 256>>>(QKV, Kpk);
    pack_vt<<<BB*NKV*32*16*4*32/256, 256>>>(QKV, Vtp);

    // flash attention — writes packed A-frags directly
    flash_mma<<<dim3(NH, BB, SS/128), 256>>>(Qpk, Kpk, Vtp, Apk);

    // output projection
    pack_b<<<(HIDDEN/8)*((NH*HD)/8)*32/256, 256>>>(wo, Wop, HIDDEN, NH*HD);
    gemm_fp<<<pgrid, 256>>>(Apk, Wop, out, MROWS, HIDDEN, NH*HD);
}